// round 1
// baseline (speedup 1.0000x reference)
#include <cuda_runtime.h>
#include <math.h>

#define Bsz   32
#define Ssz   1024
#define Dsz   1280
#define CRS   768
#define HEADS 20
#define HD    64
#define NTOK  16
#define ETOK  48          // N_AOE + N_IMG + 16
#define MS    (Bsz*Ssz)   // 32768
#define SCALE 0.125f      // 1/sqrt(64)

// ---------------- scratch (device globals: allocation-free) ----------------
__device__ float g_q  [MS*Dsz];          // 167 MB
__device__ float g_z  [MS*Dsz];          // 167 MB
__device__ float g_anat[Bsz*NTOK*CRS];   // contiguous anat tokens
__device__ float g_dis [Bsz*NTOK*CRS];   // contiguous dis tokens
__device__ float g_ka [Bsz*NTOK*Dsz];
__device__ float g_va [Bsz*NTOK*Dsz];
__device__ float g_kd [Bsz*NTOK*Dsz];
__device__ float g_vd [Bsz*NTOK*Dsz];
__device__ float g_gate[Bsz*2];          // [b][0]=anat_gate, [b][1]=dis_gate

// ---------------- gather encoder tokens into contiguous buffers ------------
__global__ void gather_tokens(const float* __restrict__ enc) {
    int i = blockIdx.x * blockDim.x + threadIdx.x;          // over Bsz*NTOK*CRS
    if (i >= Bsz*NTOK*CRS) return;
    int c = i % CRS;
    int t = (i / CRS) % NTOK;
    int b = i / (CRS*NTOK);
    g_dis [i] = enc[((long)b*ETOK + t)        * CRS + c];
    g_anat[i] = enc[((long)b*ETOK + NTOK + t) * CRS + c];
}

// ---------------- per-batch gate scalars -----------------------------------
__global__ void gate_kernel(const float* __restrict__ w_gate,
                            const float* __restrict__ b_gate,
                            const float* __restrict__ anat_logit,
                            const float* __restrict__ dis_logit) {
    int b = blockIdx.x;
    __shared__ float red[256];
    float partial = 0.f;
    for (int c = threadIdx.x; c < CRS; c += 256) {
        float s = 0.f;
        #pragma unroll
        for (int t = 0; t < NTOK; t++)
            s += g_dis[(b*NTOK + t)*CRS + c];
        partial += (s * (1.0f/NTOK)) * w_gate[c];
    }
    red[threadIdx.x] = partial;
    __syncthreads();
    for (int off = 128; off > 0; off >>= 1) {
        if (threadIdx.x < off) red[threadIdx.x] += red[threadIdx.x + off];
        __syncthreads();
    }
    if (threadIdx.x == 0) {
        float shift = red[0] + b_gate[0];
        float al = anat_logit[0], dl = dis_logit[0];
        g_gate[b*2+0] = 1.0f / (1.0f + expf(-(al - shift)));
        g_gate[b*2+1] = 1.0f / (1.0f + expf(-(dl + shift)));
    }
}

// ---------------- SGEMM: C[m,n] = sum_k A[m,k]*W[n,k] (+bias +residual) -----
// A: M x K row-major, W: N x K row-major. M%128==0, N%128==0, K%8==0.
#define BM 128
#define BN 128
#define BK 8
#define TM 8
#define TN 8
__global__ __launch_bounds__(256)
void sgemm_nt(const float* __restrict__ A, const float* __restrict__ W,
              float* __restrict__ C, int M, int N, int K,
              const float* __restrict__ bias, const float* __restrict__ res) {
    __shared__ float As[BK][BM];
    __shared__ float Bs[BK][BN];

    const int tid = threadIdx.x;
    const int bm = blockIdx.y * BM;
    const int bn = blockIdx.x * BN;

    const int ldRow = tid >> 1;          // 0..127
    const int ldCol = (tid & 1) * 4;     // 0 or 4

    const int tr = (tid >> 4) * TM;      // 0..120 step 8
    const int tc = (tid & 15) * TN;      // 0..120 step 8

    const float* Ab = A + (long)bm * K;
    const float* Wb = W + (long)bn * K;

    float acc[TM][TN];
    #pragma unroll
    for (int i = 0; i < TM; i++)
        #pragma unroll
        for (int j = 0; j < TN; j++) acc[i][j] = 0.f;

    for (int k0 = 0; k0 < K; k0 += BK) {
        float4 a4 = *(const float4*)(Ab + (long)ldRow * K + k0 + ldCol);
        As[ldCol+0][ldRow] = a4.x;
        As[ldCol+1][ldRow] = a4.y;
        As[ldCol+2][ldRow] = a4.z;
        As[ldCol+3][ldRow] = a4.w;
        float4 b4 = *(const float4*)(Wb + (long)ldRow * K + k0 + ldCol);
        Bs[ldCol+0][ldRow] = b4.x;
        Bs[ldCol+1][ldRow] = b4.y;
        Bs[ldCol+2][ldRow] = b4.z;
        Bs[ldCol+3][ldRow] = b4.w;
        __syncthreads();

        #pragma unroll
        for (int k = 0; k < BK; k++) {
            float4 m0 = *(const float4*)&As[k][tr];
            float4 m1 = *(const float4*)&As[k][tr+4];
            float4 n0 = *(const float4*)&Bs[k][tc];
            float4 n1 = *(const float4*)&Bs[k][tc+4];
            float rm[TM] = {m0.x,m0.y,m0.z,m0.w,m1.x,m1.y,m1.z,m1.w};
            float rn[TN] = {n0.x,n0.y,n0.z,n0.w,n1.x,n1.y,n1.z,n1.w};
            #pragma unroll
            for (int i = 0; i < TM; i++)
                #pragma unroll
                for (int j = 0; j < TN; j++)
                    acc[i][j] = fmaf(rm[i], rn[j], acc[i][j]);
        }
        __syncthreads();
    }

    // epilogue
    #pragma unroll
    for (int i = 0; i < TM; i++) {
        long row = bm + tr + i;
        float* Crow = C + row * N + bn + tc;
        #pragma unroll
        for (int j4 = 0; j4 < TN; j4 += 4) {
            float4 v = make_float4(acc[i][j4], acc[i][j4+1], acc[i][j4+2], acc[i][j4+3]);
            if (bias) {
                const float* bp = bias + bn + tc + j4;
                v.x += bp[0]; v.y += bp[1]; v.z += bp[2]; v.w += bp[3];
            }
            if (res) {
                float4 r = *(const float4*)(res + row * N + bn + tc + j4);
                v.x += r.x; v.y += r.y; v.z += r.z; v.w += r.w;
            }
            *(float4*)(Crow + j4) = v;
        }
    }
}

// ---------------- fused dual attention + gating -----------------------------
// grid: (S/128, HEADS, B), block 128. One thread = one query position.
__global__ __launch_bounds__(128)
void attn_kernel() {
    __shared__ float ka[NTOK][HD], va[NTOK][HD], kd[NTOK][HD], vd[NTOK][HD];
    const int b = blockIdx.z, h = blockIdx.y;
    const int s = blockIdx.x * 128 + threadIdx.x;

    for (int i = threadIdx.x; i < NTOK*HD; i += 128) {
        int t = i / HD, d = i % HD;
        long src = (long)(b*NTOK + t) * Dsz + h*HD + d;
        ka[t][d] = g_ka[src];
        va[t][d] = g_va[src];
        kd[t][d] = g_kd[src];
        vd[t][d] = g_vd[src];
    }
    __syncthreads();

    const float ga = g_gate[b*2+0];
    const float gd = g_gate[b*2+1];

    float q[HD];
    const float* qp = g_q + ((long)(b*Ssz + s)) * Dsz + h*HD;
    #pragma unroll
    for (int d = 0; d < HD; d += 4) {
        float4 v = *(const float4*)(qp + d);
        q[d] = v.x; q[d+1] = v.y; q[d+2] = v.z; q[d+3] = v.w;
    }

    float out[HD];
    #pragma unroll
    for (int d = 0; d < HD; d++) out[d] = 0.f;

    float sc[NTOK];

    // ---- anat branch ----
    float mx = -1e30f;
    #pragma unroll
    for (int j = 0; j < NTOK; j++) {
        float s2 = 0.f;
        #pragma unroll
        for (int d = 0; d < HD; d++) s2 = fmaf(q[d], ka[j][d], s2);
        sc[j] = s2 * SCALE;
        mx = fmaxf(mx, sc[j]);
    }
    float sum = 0.f;
    #pragma unroll
    for (int j = 0; j < NTOK; j++) { sc[j] = expf(sc[j] - mx); sum += sc[j]; }
    float inv = ga / sum;
    #pragma unroll
    for (int j = 0; j < NTOK; j++) {
        float p = sc[j] * inv;
        #pragma unroll
        for (int d = 0; d < HD; d++) out[d] = fmaf(p, va[j][d], out[d]);
    }

    // ---- dis branch ----
    mx = -1e30f;
    #pragma unroll
    for (int j = 0; j < NTOK; j++) {
        float s2 = 0.f;
        #pragma unroll
        for (int d = 0; d < HD; d++) s2 = fmaf(q[d], kd[j][d], s2);
        sc[j] = s2 * SCALE;
        mx = fmaxf(mx, sc[j]);
    }
    sum = 0.f;
    #pragma unroll
    for (int j = 0; j < NTOK; j++) { sc[j] = expf(sc[j] - mx); sum += sc[j]; }
    inv = gd / sum;
    #pragma unroll
    for (int j = 0; j < NTOK; j++) {
        float p = sc[j] * inv;
        #pragma unroll
        for (int d = 0; d < HD; d++) out[d] = fmaf(p, vd[j][d], out[d]);
    }

    float* zp = g_z + ((long)(b*Ssz + s)) * Dsz + h*HD;
    #pragma unroll
    for (int d = 0; d < HD; d += 4)
        *(float4*)(zp + d) = make_float4(out[d], out[d+1], out[d+2], out[d+3]);
}

// ---------------- launch ----------------------------------------------------
extern "C" void kernel_launch(void* const* d_in, const int* in_sizes, int n_in,
                              void* d_out, int out_size) {
    const float* hidden  = (const float*)d_in[0];   // (B,S,D)
    const float* enc     = (const float*)d_in[1];   // (B,48,CROSS)
    const float* w_q     = (const float*)d_in[2];   // (D,D)
    const float* w_k     = (const float*)d_in[3];   // (D,CROSS)
    const float* w_v     = (const float*)d_in[4];
    const float* w_k_dis = (const float*)d_in[5];
    const float* w_v_dis = (const float*)d_in[6];
    const float* w_gate  = (const float*)d_in[7];   // (1,CROSS)
    const float* b_gate  = (const float*)d_in[8];   // (1,)
    const float* a_logit = (const float*)d_in[9];   // scalar
    const float* d_logit = (const float*)d_in[10];  // scalar
    const float* w_out   = (const float*)d_in[11];  // (D,D)
    const float* b_out   = (const float*)d_in[12];  // (D,)
    float* out = (float*)d_out;                     // (B,S,D)

    float *anat_p, *dis_p, *ka_p, *va_p, *kd_p, *vd_p, *q_p, *z_p;
    cudaGetSymbolAddress((void**)&anat_p, g_anat);
    cudaGetSymbolAddress((void**)&dis_p,  g_dis);
    cudaGetSymbolAddress((void**)&ka_p,   g_ka);
    cudaGetSymbolAddress((void**)&va_p,   g_va);
    cudaGetSymbolAddress((void**)&kd_p,   g_kd);
    cudaGetSymbolAddress((void**)&vd_p,   g_vd);
    cudaGetSymbolAddress((void**)&q_p,    g_q);
    cudaGetSymbolAddress((void**)&z_p,    g_z);

    // 1. gather tokens
    {
        int n = Bsz*NTOK*CRS;
        gather_tokens<<<(n + 255)/256, 256>>>(enc);
    }
    // 2. gates
    gate_kernel<<<Bsz, 256>>>(w_gate, b_gate, a_logit, d_logit);

    // 3. KV projections: M=512, N=1280, K=768
    {
        dim3 grid(Dsz/BN, (Bsz*NTOK)/BM);
        sgemm_nt<<<grid, 256>>>(anat_p, w_k,     ka_p, Bsz*NTOK, Dsz, CRS, nullptr, nullptr);
        sgemm_nt<<<grid, 256>>>(anat_p, w_v,     va_p, Bsz*NTOK, Dsz, CRS, nullptr, nullptr);
        sgemm_nt<<<grid, 256>>>(dis_p,  w_k_dis, kd_p, Bsz*NTOK, Dsz, CRS, nullptr, nullptr);
        sgemm_nt<<<grid, 256>>>(dis_p,  w_v_dis, vd_p, Bsz*NTOK, Dsz, CRS, nullptr, nullptr);
    }
    // 4. Q projection: M=32768, N=1280, K=1280
    {
        dim3 grid(Dsz/BN, MS/BM);
        sgemm_nt<<<grid, 256>>>(hidden, w_q, q_p, MS, Dsz, Dsz, nullptr, nullptr);
    }
    // 5. attention + gating
    {
        dim3 grid(Ssz/128, HEADS, Bsz);
        attn_kernel<<<grid, 128>>>();
    }
    // 6. out projection + bias + residual
    {
        dim3 grid(Dsz/BN, MS/BM);
        sgemm_nt<<<grid, 256>>>(z_p, w_out, out, MS, Dsz, Dsz, b_out, hidden);
    }
}

// round 2
// speedup vs baseline: 1.0012x; 1.0012x over previous
#include <cuda_runtime.h>
#include <math.h>

#define Bsz   32
#define Ssz   1024
#define Dsz   1280
#define CRS   768
#define HEADS 20
#define HD    64
#define NTOK  16
#define ETOK  48          // N_AOE + N_IMG + 16
#define MS    (Bsz*Ssz)   // 32768
#define SCALE 0.125f      // 1/sqrt(64)

// ---------------- scratch (device globals: allocation-free) ----------------
__device__ float g_q  [MS*Dsz];          // 167 MB
__device__ float g_z  [MS*Dsz];          // 167 MB
__device__ float g_anat[Bsz*NTOK*CRS];   // contiguous anat tokens
__device__ float g_dis [Bsz*NTOK*CRS];   // contiguous dis tokens
__device__ float g_ka [Bsz*NTOK*Dsz];
__device__ float g_va [Bsz*NTOK*Dsz];
__device__ float g_kd [Bsz*NTOK*Dsz];
__device__ float g_vd [Bsz*NTOK*Dsz];
__device__ float g_gate[Bsz*2];          // [b][0]=anat_gate, [b][1]=dis_gate

// ---------------- gather encoder tokens into contiguous buffers ------------
__global__ void gather_tokens(const float* __restrict__ enc) {
    int i = blockIdx.x * blockDim.x + threadIdx.x;          // over Bsz*NTOK*CRS
    if (i >= Bsz*NTOK*CRS) return;
    int c = i % CRS;
    int t = (i / CRS) % NTOK;
    int b = i / (CRS*NTOK);
    g_dis [i] = enc[((long)b*ETOK + t)        * CRS + c];
    g_anat[i] = enc[((long)b*ETOK + NTOK + t) * CRS + c];
}

// ---------------- per-batch gate scalars -----------------------------------
__global__ void gate_kernel(const float* __restrict__ w_gate,
                            const float* __restrict__ b_gate,
                            const float* __restrict__ anat_logit,
                            const float* __restrict__ dis_logit) {
    int b = blockIdx.x;
    __shared__ float red[256];
    float partial = 0.f;
    for (int c = threadIdx.x; c < CRS; c += 256) {
        float s = 0.f;
        #pragma unroll
        for (int t = 0; t < NTOK; t++)
            s += g_dis[(b*NTOK + t)*CRS + c];
        partial += (s * (1.0f/NTOK)) * w_gate[c];
    }
    red[threadIdx.x] = partial;
    __syncthreads();
    for (int off = 128; off > 0; off >>= 1) {
        if (threadIdx.x < off) red[threadIdx.x] += red[threadIdx.x + off];
        __syncthreads();
    }
    if (threadIdx.x == 0) {
        float shift = red[0] + b_gate[0];
        float al = anat_logit[0], dl = dis_logit[0];
        g_gate[b*2+0] = 1.0f / (1.0f + expf(-(al - shift)));
        g_gate[b*2+1] = 1.0f / (1.0f + expf(-(dl + shift)));
    }
}

// ---------------- SGEMM: C[m,n] = sum_k A[m,k]*W[n,k] (+bias +residual) -----
// A: M x K row-major, W: N x K row-major. M%128==0, N%128==0, K%8==0.
#define BM 128
#define BN 128
#define BK 8
#define TM 8
#define TN 8
__global__ __launch_bounds__(256)
void sgemm_nt(const float* __restrict__ A, const float* __restrict__ W,
              float* __restrict__ C, int M, int N, int K,
              const float* __restrict__ bias, const float* __restrict__ res) {
    __shared__ float As[BK][BM];
    __shared__ float Bs[BK][BN];

    const int tid = threadIdx.x;
    const int bm = blockIdx.y * BM;
    const int bn = blockIdx.x * BN;

    const int ldRow = tid >> 1;          // 0..127
    const int ldCol = (tid & 1) * 4;     // 0 or 4

    const int tr = (tid >> 4) * TM;      // 0..120 step 8
    const int tc = (tid & 15) * TN;      // 0..120 step 8

    const float* Ab = A + (long)bm * K;
    const float* Wb = W + (long)bn * K;

    float acc[TM][TN];
    #pragma unroll
    for (int i = 0; i < TM; i++)
        #pragma unroll
        for (int j = 0; j < TN; j++) acc[i][j] = 0.f;

    for (int k0 = 0; k0 < K; k0 += BK) {
        float4 a4 = *(const float4*)(Ab + (long)ldRow * K + k0 + ldCol);
        As[ldCol+0][ldRow] = a4.x;
        As[ldCol+1][ldRow] = a4.y;
        As[ldCol+2][ldRow] = a4.z;
        As[ldCol+3][ldRow] = a4.w;
        float4 b4 = *(const float4*)(Wb + (long)ldRow * K + k0 + ldCol);
        Bs[ldCol+0][ldRow] = b4.x;
        Bs[ldCol+1][ldRow] = b4.y;
        Bs[ldCol+2][ldRow] = b4.z;
        Bs[ldCol+3][ldRow] = b4.w;
        __syncthreads();

        #pragma unroll
        for (int k = 0; k < BK; k++) {
            float4 m0 = *(const float4*)&As[k][tr];
            float4 m1 = *(const float4*)&As[k][tr+4];
            float4 n0 = *(const float4*)&Bs[k][tc];
            float4 n1 = *(const float4*)&Bs[k][tc+4];
            float rm[TM] = {m0.x,m0.y,m0.z,m0.w,m1.x,m1.y,m1.z,m1.w};
            float rn[TN] = {n0.x,n0.y,n0.z,n0.w,n1.x,n1.y,n1.z,n1.w};
            #pragma unroll
            for (int i = 0; i < TM; i++)
                #pragma unroll
                for (int j = 0; j < TN; j++)
                    acc[i][j] = fmaf(rm[i], rn[j], acc[i][j]);
        }
        __syncthreads();
    }

    // epilogue
    #pragma unroll
    for (int i = 0; i < TM; i++) {
        long row = bm + tr + i;
        float* Crow = C + row * N + bn + tc;
        #pragma unroll
        for (int j4 = 0; j4 < TN; j4 += 4) {
            float4 v = make_float4(acc[i][j4], acc[i][j4+1], acc[i][j4+2], acc[i][j4+3]);
            if (bias) {
                const float* bp = bias + bn + tc + j4;
                v.x += bp[0]; v.y += bp[1]; v.z += bp[2]; v.w += bp[3];
            }
            if (res) {
                float4 r = *(const float4*)(res + row * N + bn + tc + j4);
                v.x += r.x; v.y += r.y; v.z += r.z; v.w += r.w;
            }
            *(float4*)(Crow + j4) = v;
        }
    }
}

// ---------------- fused dual attention + gating -----------------------------
// grid: (S/128, HEADS, B), block 128. One thread = one query position.
__global__ __launch_bounds__(128)
void attn_kernel() {
    __shared__ float ka[NTOK][HD], va[NTOK][HD], kd[NTOK][HD], vd[NTOK][HD];
    const int b = blockIdx.z, h = blockIdx.y;
    const int s = blockIdx.x * 128 + threadIdx.x;

    for (int i = threadIdx.x; i < NTOK*HD; i += 128) {
        int t = i / HD, d = i % HD;
        long src = (long)(b*NTOK + t) * Dsz + h*HD + d;
        ka[t][d] = g_ka[src];
        va[t][d] = g_va[src];
        kd[t][d] = g_kd[src];
        vd[t][d] = g_vd[src];
    }
    __syncthreads();

    const float ga = g_gate[b*2+0];
    const float gd = g_gate[b*2+1];

    float q[HD];
    const float* qp = g_q + ((long)(b*Ssz + s)) * Dsz + h*HD;
    #pragma unroll
    for (int d = 0; d < HD; d += 4) {
        float4 v = *(const float4*)(qp + d);
        q[d] = v.x; q[d+1] = v.y; q[d+2] = v.z; q[d+3] = v.w;
    }

    float out[HD];
    #pragma unroll
    for (int d = 0; d < HD; d++) out[d] = 0.f;

    float sc[NTOK];

    // ---- anat branch ----
    float mx = -1e30f;
    #pragma unroll
    for (int j = 0; j < NTOK; j++) {
        float s2 = 0.f;
        #pragma unroll
        for (int d = 0; d < HD; d++) s2 = fmaf(q[d], ka[j][d], s2);
        sc[j] = s2 * SCALE;
        mx = fmaxf(mx, sc[j]);
    }
    float sum = 0.f;
    #pragma unroll
    for (int j = 0; j < NTOK; j++) { sc[j] = expf(sc[j] - mx); sum += sc[j]; }
    float inv = ga / sum;
    #pragma unroll
    for (int j = 0; j < NTOK; j++) {
        float p = sc[j] * inv;
        #pragma unroll
        for (int d = 0; d < HD; d++) out[d] = fmaf(p, va[j][d], out[d]);
    }

    // ---- dis branch ----
    mx = -1e30f;
    #pragma unroll
    for (int j = 0; j < NTOK; j++) {
        float s2 = 0.f;
        #pragma unroll
        for (int d = 0; d < HD; d++) s2 = fmaf(q[d], kd[j][d], s2);
        sc[j] = s2 * SCALE;
        mx = fmaxf(mx, sc[j]);
    }
    sum = 0.f;
    #pragma unroll
    for (int j = 0; j < NTOK; j++) { sc[j] = expf(sc[j] - mx); sum += sc[j]; }
    inv = gd / sum;
    #pragma unroll
    for (int j = 0; j < NTOK; j++) {
        float p = sc[j] * inv;
        #pragma unroll
        for (int d = 0; d < HD; d++) out[d] = fmaf(p, vd[j][d], out[d]);
    }

    float* zp = g_z + ((long)(b*Ssz + s)) * Dsz + h*HD;
    #pragma unroll
    for (int d = 0; d < HD; d += 4)
        *(float4*)(zp + d) = make_float4(out[d], out[d+1], out[d+2], out[d+3]);
}

// ---------------- launch ----------------------------------------------------
extern "C" void kernel_launch(void* const* d_in, const int* in_sizes, int n_in,
                              void* d_out, int out_size) {
    const float* hidden  = (const float*)d_in[0];   // (B,S,D)
    const float* enc     = (const float*)d_in[1];   // (B,48,CROSS)
    const float* w_q     = (const float*)d_in[2];   // (D,D)
    const float* w_k     = (const float*)d_in[3];   // (D,CROSS)
    const float* w_v     = (const float*)d_in[4];
    const float* w_k_dis = (const float*)d_in[5];
    const float* w_v_dis = (const float*)d_in[6];
    const float* w_gate  = (const float*)d_in[7];   // (1,CROSS)
    const float* b_gate  = (const float*)d_in[8];   // (1,)
    const float* a_logit = (const float*)d_in[9];   // scalar
    const float* d_logit = (const float*)d_in[10];  // scalar
    const float* w_out   = (const float*)d_in[11];  // (D,D)
    const float* b_out   = (const float*)d_in[12];  // (D,)
    float* out = (float*)d_out;                     // (B,S,D)

    float *anat_p, *dis_p, *ka_p, *va_p, *kd_p, *vd_p, *q_p, *z_p;
    cudaGetSymbolAddress((void**)&anat_p, g_anat);
    cudaGetSymbolAddress((void**)&dis_p,  g_dis);
    cudaGetSymbolAddress((void**)&ka_p,   g_ka);
    cudaGetSymbolAddress((void**)&va_p,   g_va);
    cudaGetSymbolAddress((void**)&kd_p,   g_kd);
    cudaGetSymbolAddress((void**)&vd_p,   g_vd);
    cudaGetSymbolAddress((void**)&q_p,    g_q);
    cudaGetSymbolAddress((void**)&z_p,    g_z);

    // 1. gather tokens
    {
        int n = Bsz*NTOK*CRS;
        gather_tokens<<<(n + 255)/256, 256>>>(enc);
    }
    // 2. gates
    gate_kernel<<<Bsz, 256>>>(w_gate, b_gate, a_logit, d_logit);

    // 3. KV projections: M=512, N=1280, K=768
    {
        dim3 grid(Dsz/BN, (Bsz*NTOK)/BM);
        sgemm_nt<<<grid, 256>>>(anat_p, w_k,     ka_p, Bsz*NTOK, Dsz, CRS, nullptr, nullptr);
        sgemm_nt<<<grid, 256>>>(anat_p, w_v,     va_p, Bsz*NTOK, Dsz, CRS, nullptr, nullptr);
        sgemm_nt<<<grid, 256>>>(dis_p,  w_k_dis, kd_p, Bsz*NTOK, Dsz, CRS, nullptr, nullptr);
        sgemm_nt<<<grid, 256>>>(dis_p,  w_v_dis, vd_p, Bsz*NTOK, Dsz, CRS, nullptr, nullptr);
    }
    // 4. Q projection: M=32768, N=1280, K=1280
    {
        dim3 grid(Dsz/BN, MS/BM);
        sgemm_nt<<<grid, 256>>>(hidden, w_q, q_p, MS, Dsz, Dsz, nullptr, nullptr);
    }
    // 5. attention + gating
    {
        dim3 grid(Ssz/128, HEADS, Bsz);
        attn_kernel<<<grid, 128>>>();
    }
    // 6. out projection + bias + residual
    {
        dim3 grid(Dsz/BN, MS/BM);
        sgemm_nt<<<grid, 256>>>(z_p, w_out, out, MS, Dsz, Dsz, b_out, hidden);
    }
}

// round 4
// speedup vs baseline: 3.3244x; 3.3204x over previous
#include <cuda_runtime.h>
#include <math.h>
#include <stdint.h>

#define Bsz   32
#define Ssz   1024
#define Dsz   1280
#define CRS   768
#define HEADS 20
#define HD    64
#define NTOK  16
#define ETOK  48
#define MS    (Bsz*Ssz)
#define SCALE 0.125f

// ---------------- scratch (device globals: allocation-free) ----------------
__device__ float g_q  [MS*Dsz];
__device__ float g_z  [MS*Dsz];
__device__ float g_hid[MS*Dsz];          // tf32-rounded hidden
__device__ float g_anat[Bsz*NTOK*CRS];
__device__ float g_dis [Bsz*NTOK*CRS];
__device__ float g_ka [Bsz*NTOK*Dsz];
__device__ float g_va [Bsz*NTOK*Dsz];
__device__ float g_kd [Bsz*NTOK*Dsz];
__device__ float g_vd [Bsz*NTOK*Dsz];
__device__ float g_gate[Bsz*2];
__device__ float g_wq  [Dsz*Dsz];
__device__ float g_wout[Dsz*Dsz];
__device__ float g_wka [Dsz*CRS];
__device__ float g_wva [Dsz*CRS];
__device__ float g_wkd [Dsz*CRS];
__device__ float g_wvd [Dsz*CRS];

// ---------------- helpers ---------------------------------------------------
__device__ __forceinline__ uint32_t smem_u32(const void* p) {
    uint32_t a;
    asm("{ .reg .u64 t; cvta.to.shared.u64 t, %1; cvt.u32.u64 %0, t; }" : "=r"(a) : "l"(p));
    return a;
}
__device__ __forceinline__ float tf32r(float x) {
    uint32_t o;
    asm("cvt.rna.tf32.f32 %0, %1;" : "=r"(o) : "f"(x));
    return __uint_as_float(o);
}
__device__ __forceinline__ void cp16(uint32_t dst, const void* src) {
    asm volatile("cp.async.cg.shared.global [%0], [%1], 16;" :: "r"(dst), "l"(src));
}
#define CP_COMMIT() asm volatile("cp.async.commit_group;" ::: "memory")

// ---------------- tf32 mma.sync GEMM: C[m,n] = sum_k A[m,k]*W[n,k] ----------
// BM=BN=128, BK=32. 8 warps (2x4), warp tile 64x32. Double-buffered cp.async.
#define LDA 36
#define TILE_F (128*LDA)            // floats per A or B tile
#define STAGE_F (2*TILE_F)
#define GEMM_SMEM (2*STAGE_F*4)     // 73728 bytes

__device__ __forceinline__ void mma8(float* d, const uint32_t* a, const uint32_t* b) {
    asm volatile(
        "mma.sync.aligned.m16n8k8.row.col.f32.tf32.tf32.f32 "
        "{%0,%1,%2,%3}, {%4,%5,%6,%7}, {%8,%9}, {%0,%1,%2,%3};"
        : "+f"(d[0]), "+f"(d[1]), "+f"(d[2]), "+f"(d[3])
        : "r"(a[0]), "r"(a[1]), "r"(a[2]), "r"(a[3]), "r"(b[0]), "r"(b[1]));
}

__global__ __launch_bounds__(256, 2)
void gemm_mma(const float* __restrict__ A, const float* __restrict__ W,
              float* __restrict__ C, int M, int N, int K,
              const float* __restrict__ bias, const float* __restrict__ res) {
    extern __shared__ float sm[];
    const int t = threadIdx.x;
    const int lane = t & 31, wid = t >> 5;
    const int warp_m = wid >> 2, warp_n = wid & 3;
    const int bm = blockIdx.y * 128, bn = blockIdx.x * 128;
    const int NIT = K / 32;
    const uint32_t sbase = smem_u32(sm);

    float acc[4][4][4];
    #pragma unroll
    for (int i = 0; i < 4; i++)
        #pragma unroll
        for (int j = 0; j < 4; j++)
            #pragma unroll
            for (int r = 0; r < 4; r++) acc[i][j][r] = 0.f;

    // ---- stage load (A rows bm..bm+127, W rows bn..bn+127, cols k0..k0+31)
    #define LOAD_STAGE(IT, S) do {                                             \
        const float* Ab = A + (long)bm * K + (IT) * 32;                        \
        const float* Wb = W + (long)bn * K + (IT) * 32;                        \
        uint32_t dA = sbase + (S) * (STAGE_F * 4);                             \
        uint32_t dB = dA + TILE_F * 4;                                         \
        _Pragma("unroll")                                                      \
        for (int i = 0; i < 4; i++) {                                          \
            int idx = i * 256 + t; int row = idx >> 3, g = idx & 7;            \
            cp16(dA + row * (LDA*4) + g * 16, Ab + (long)row * K + g * 4);     \
        }                                                                      \
        _Pragma("unroll")                                                      \
        for (int i = 0; i < 4; i++) {                                          \
            int idx = i * 256 + t; int row = idx >> 3, g = idx & 7;            \
            cp16(dB + row * (LDA*4) + g * 16, Wb + (long)row * K + g * 4);     \
        }                                                                      \
        CP_COMMIT();                                                           \
    } while (0)

    LOAD_STAGE(0, 0);

    for (int it = 0; it < NIT; it++) {
        int s = it & 1;
        if (it + 1 < NIT) {
            LOAD_STAGE(it + 1, (it + 1) & 1);
            asm volatile("cp.async.wait_group 1;" ::: "memory");
        } else {
            asm volatile("cp.async.wait_group 0;" ::: "memory");
        }
        __syncthreads();

        const float* As = sm + s * STAGE_F;
        const float* Bs = As + TILE_F;
        #pragma unroll
        for (int ks = 0; ks < 4; ks++) {
            uint32_t a[4][4], b[4][2];
            const int c0 = ks * 8 + (lane & 3);
            const int r  = lane >> 2;
            #pragma unroll
            for (int mt = 0; mt < 4; mt++) {
                int row = warp_m * 64 + mt * 16 + r;
                a[mt][0] = __float_as_uint(As[row * LDA + c0]);
                a[mt][1] = __float_as_uint(As[(row + 8) * LDA + c0]);
                a[mt][2] = __float_as_uint(As[row * LDA + c0 + 4]);
                a[mt][3] = __float_as_uint(As[(row + 8) * LDA + c0 + 4]);
            }
            #pragma unroll
            for (int nt = 0; nt < 4; nt++) {
                int rowb = warp_n * 32 + nt * 8 + r;
                b[nt][0] = __float_as_uint(Bs[rowb * LDA + c0]);
                b[nt][1] = __float_as_uint(Bs[rowb * LDA + c0 + 4]);
            }
            #pragma unroll
            for (int mt = 0; mt < 4; mt++)
                #pragma unroll
                for (int nt = 0; nt < 4; nt++)
                    mma8(acc[mt][nt], a[mt], b[nt]);
        }
        __syncthreads();
    }

    // ---- epilogue
    #pragma unroll
    for (int mt = 0; mt < 4; mt++) {
        #pragma unroll
        for (int nt = 0; nt < 4; nt++) {
            int row = bm + warp_m * 64 + mt * 16 + (lane >> 2);
            int col = bn + warp_n * 32 + nt * 8 + 2 * (lane & 3);
            float2 v0 = make_float2(acc[mt][nt][0], acc[mt][nt][1]);
            float2 v1 = make_float2(acc[mt][nt][2], acc[mt][nt][3]);
            if (bias) {
                float2 bb = *(const float2*)(bias + col);
                v0.x += bb.x; v0.y += bb.y; v1.x += bb.x; v1.y += bb.y;
            }
            if (res) {
                float2 r0 = *(const float2*)(res + (long)row * N + col);
                float2 r1 = *(const float2*)(res + (long)(row + 8) * N + col);
                v0.x += r0.x; v0.y += r0.y; v1.x += r1.x; v1.y += r1.y;
            }
            *(float2*)(C + (long)row * N + col) = v0;
            *(float2*)(C + (long)(row + 8) * N + col) = v1;
        }
    }
}

// ---------------- tf32 rounding prepass -------------------------------------
__global__ void round_tf32(const float* __restrict__ x, float* __restrict__ y, int n4) {
    int i = blockIdx.x * blockDim.x + threadIdx.x;
    if (i >= n4) return;
    float4 v = ((const float4*)x)[i];
    v.x = tf32r(v.x); v.y = tf32r(v.y); v.z = tf32r(v.z); v.w = tf32r(v.w);
    ((float4*)y)[i] = v;
}

// ---------------- gather encoder tokens (rounded) ---------------------------
__global__ void gather_tokens(const float* __restrict__ enc) {
    int i = blockIdx.x * blockDim.x + threadIdx.x;
    if (i >= Bsz*NTOK*CRS) return;
    int c = i % CRS;
    int tt = (i / CRS) % NTOK;
    int b = i / (CRS*NTOK);
    g_dis [i] = tf32r(enc[((long)b*ETOK + tt)        * CRS + c]);
    g_anat[i] = tf32r(enc[((long)b*ETOK + NTOK + tt) * CRS + c]);
}

// ---------------- per-batch gate scalars -----------------------------------
__global__ void gate_kernel(const float* __restrict__ w_gate,
                            const float* __restrict__ b_gate,
                            const float* __restrict__ anat_logit,
                            const float* __restrict__ dis_logit) {
    int b = blockIdx.x;
    __shared__ float red[256];
    float partial = 0.f;
    for (int c = threadIdx.x; c < CRS; c += 256) {
        float s = 0.f;
        #pragma unroll
        for (int t = 0; t < NTOK; t++) s += g_dis[(b*NTOK + t)*CRS + c];
        partial += (s * (1.0f/NTOK)) * w_gate[c];
    }
    red[threadIdx.x] = partial;
    __syncthreads();
    for (int off = 128; off > 0; off >>= 1) {
        if (threadIdx.x < off) red[threadIdx.x] += red[threadIdx.x + off];
        __syncthreads();
    }
    if (threadIdx.x == 0) {
        float shift = red[0] + b_gate[0];
        g_gate[b*2+0] = 1.0f / (1.0f + expf(-(anat_logit[0] - shift)));
        g_gate[b*2+1] = 1.0f / (1.0f + expf(-(dis_logit[0]  + shift)));
    }
}

// ---------------- fused dual attention + gating (emits tf32-rounded z) ------
__global__ __launch_bounds__(128)
void attn_kernel() {
    __shared__ float ka[NTOK][HD], va[NTOK][HD], kd[NTOK][HD], vd[NTOK][HD];
    const int b = blockIdx.z, h = blockIdx.y;
    const int s = blockIdx.x * 128 + threadIdx.x;

    for (int i = threadIdx.x; i < NTOK*HD; i += 128) {
        int t = i / HD, d = i % HD;
        long src = (long)(b*NTOK + t) * Dsz + h*HD + d;
        ka[t][d] = g_ka[src];  va[t][d] = g_va[src];
        kd[t][d] = g_kd[src];  vd[t][d] = g_vd[src];
    }
    __syncthreads();

    const float ga = g_gate[b*2+0];
    const float gd = g_gate[b*2+1];

    float q[HD];
    const float* qp = g_q + ((long)(b*Ssz + s)) * Dsz + h*HD;
    #pragma unroll
    for (int d = 0; d < HD; d += 4) {
        float4 v = *(const float4*)(qp + d);
        q[d] = v.x; q[d+1] = v.y; q[d+2] = v.z; q[d+3] = v.w;
    }

    float out[HD];
    #pragma unroll
    for (int d = 0; d < HD; d++) out[d] = 0.f;
    float sc[NTOK];

    float mx = -1e30f;
    #pragma unroll
    for (int j = 0; j < NTOK; j++) {
        float s2 = 0.f;
        #pragma unroll
        for (int d = 0; d < HD; d++) s2 = fmaf(q[d], ka[j][d], s2);
        sc[j] = s2 * SCALE;  mx = fmaxf(mx, sc[j]);
    }
    float sum = 0.f;
    #pragma unroll
    for (int j = 0; j < NTOK; j++) { sc[j] = expf(sc[j] - mx); sum += sc[j]; }
    float inv = ga / sum;
    #pragma unroll
    for (int j = 0; j < NTOK; j++) {
        float p = sc[j] * inv;
        #pragma unroll
        for (int d = 0; d < HD; d++) out[d] = fmaf(p, va[j][d], out[d]);
    }

    mx = -1e30f;
    #pragma unroll
    for (int j = 0; j < NTOK; j++) {
        float s2 = 0.f;
        #pragma unroll
        for (int d = 0; d < HD; d++) s2 = fmaf(q[d], kd[j][d], s2);
        sc[j] = s2 * SCALE;  mx = fmaxf(mx, sc[j]);
    }
    sum = 0.f;
    #pragma unroll
    for (int j = 0; j < NTOK; j++) { sc[j] = expf(sc[j] - mx); sum += sc[j]; }
    inv = gd / sum;
    #pragma unroll
    for (int j = 0; j < NTOK; j++) {
        float p = sc[j] * inv;
        #pragma unroll
        for (int d = 0; d < HD; d++) out[d] = fmaf(p, vd[j][d], out[d]);
    }

    float* zp = g_z + ((long)(b*Ssz + s)) * Dsz + h*HD;
    #pragma unroll
    for (int d = 0; d < HD; d += 4)
        *(float4*)(zp + d) = make_float4(tf32r(out[d]),   tf32r(out[d+1]),
                                         tf32r(out[d+2]), tf32r(out[d+3]));
}

// ---------------- launch ----------------------------------------------------
extern "C" void kernel_launch(void* const* d_in, const int* in_sizes, int n_in,
                              void* d_out, int out_size) {
    const float* hidden  = (const float*)d_in[0];
    const float* enc     = (const float*)d_in[1];
    const float* w_q     = (const float*)d_in[2];
    const float* w_k     = (const float*)d_in[3];
    const float* w_v     = (const float*)d_in[4];
    const float* w_k_dis = (const float*)d_in[5];
    const float* w_v_dis = (const float*)d_in[6];
    const float* w_gate  = (const float*)d_in[7];
    const float* b_gate  = (const float*)d_in[8];
    const float* a_logit = (const float*)d_in[9];
    const float* d_logit = (const float*)d_in[10];
    const float* w_out   = (const float*)d_in[11];
    const float* b_out   = (const float*)d_in[12];
    float* out = (float*)d_out;

    float *anat_p, *dis_p, *ka_p, *va_p, *kd_p, *vd_p, *q_p, *z_p, *hid_p;
    float *wq_p, *wout_p, *wka_p, *wva_p, *wkd_p, *wvd_p;
    cudaGetSymbolAddress((void**)&anat_p, g_anat);
    cudaGetSymbolAddress((void**)&dis_p,  g_dis);
    cudaGetSymbolAddress((void**)&ka_p,   g_ka);
    cudaGetSymbolAddress((void**)&va_p,   g_va);
    cudaGetSymbolAddress((void**)&kd_p,   g_kd);
    cudaGetSymbolAddress((void**)&vd_p,   g_vd);
    cudaGetSymbolAddress((void**)&q_p,    g_q);
    cudaGetSymbolAddress((void**)&z_p,    g_z);
    cudaGetSymbolAddress((void**)&hid_p,  g_hid);
    cudaGetSymbolAddress((void**)&wq_p,   g_wq);
    cudaGetSymbolAddress((void**)&wout_p, g_wout);
    cudaGetSymbolAddress((void**)&wka_p,  g_wka);
    cudaGetSymbolAddress((void**)&wva_p,  g_wva);
    cudaGetSymbolAddress((void**)&wkd_p,  g_wkd);
    cudaGetSymbolAddress((void**)&wvd_p,  g_wvd);

    cudaFuncSetAttribute(gemm_mma, cudaFuncAttributeMaxDynamicSharedMemorySize, GEMM_SMEM);

    // tf32 rounding prepass
    {
        int n4 = MS*Dsz/4;
        round_tf32<<<(n4 + 255)/256, 256>>>(hidden, hid_p, n4);
        int w4 = Dsz*Dsz/4;
        round_tf32<<<(w4 + 255)/256, 256>>>(w_q,   wq_p,   w4);
        round_tf32<<<(w4 + 255)/256, 256>>>(w_out, wout_p, w4);
        int k4 = Dsz*CRS/4;
        round_tf32<<<(k4 + 255)/256, 256>>>(w_k,     wka_p, k4);
        round_tf32<<<(k4 + 255)/256, 256>>>(w_v,     wva_p, k4);
        round_tf32<<<(k4 + 255)/256, 256>>>(w_k_dis, wkd_p, k4);
        round_tf32<<<(k4 + 255)/256, 256>>>(w_v_dis, wvd_p, k4);
    }
    { int n = Bsz*NTOK*CRS; gather_tokens<<<(n + 255)/256, 256>>>(enc); }
    gate_kernel<<<Bsz, 256>>>(w_gate, b_gate, a_logit, d_logit);

    // KV projections: M=512, N=1280, K=768
    {
        dim3 grid(Dsz/128, (Bsz*NTOK)/128);
        gemm_mma<<<grid, 256, GEMM_SMEM>>>(anat_p, wka_p, ka_p, Bsz*NTOK, Dsz, CRS, nullptr, nullptr);
        gemm_mma<<<grid, 256, GEMM_SMEM>>>(anat_p, wva_p, va_p, Bsz*NTOK, Dsz, CRS, nullptr, nullptr);
        gemm_mma<<<grid, 256, GEMM_SMEM>>>(dis_p,  wkd_p, kd_p, Bsz*NTOK, Dsz, CRS, nullptr, nullptr);
        gemm_mma<<<grid, 256, GEMM_SMEM>>>(dis_p,  wvd_p, vd_p, Bsz*NTOK, Dsz, CRS, nullptr, nullptr);
    }
    // Q projection: M=32768, N=1280, K=1280
    {
        dim3 grid(Dsz/128, MS/128);
        gemm_mma<<<grid, 256, GEMM_SMEM>>>(hid_p, wq_p, q_p, MS, Dsz, Dsz, nullptr, nullptr);
    }
    // attention + gating
    {
        dim3 grid(Ssz/128, HEADS, Bsz);
        attn_kernel<<<grid, 128>>>();
    }
    // out projection + bias + residual
    {
        dim3 grid(Dsz/128, MS/128);
        gemm_mma<<<grid, 256, GEMM_SMEM>>>(z_p, wout_p, out, MS, Dsz, Dsz, b_out, hidden);
    }
}

// round 5
// speedup vs baseline: 5.4380x; 1.6358x over previous
#include <cuda_runtime.h>
#include <cuda_bf16.h>
#include <math.h>
#include <stdint.h>

#define Bsz   32
#define Ssz   1024
#define Dsz   1280
#define CRS   768
#define HEADS 20
#define HD    64
#define NTOK  16
#define ETOK  48
#define MS    (Bsz*Ssz)
#define SCALE 0.125f

typedef __nv_bfloat16 bf16;

// ---------------- scratch (device globals: allocation-free) ----------------
__device__ float g_q  [MS*Dsz];            // fp32 Q (precision)
__device__ bf16  g_z  [MS*Dsz];            // bf16 attention output
__device__ bf16  g_hidb[MS*Dsz];           // bf16 hidden
__device__ bf16  g_anat[Bsz*NTOK*CRS];
__device__ bf16  g_dis [Bsz*NTOK*CRS];
__device__ float g_ka [Bsz*NTOK*Dsz];
__device__ float g_va [Bsz*NTOK*Dsz];
__device__ float g_kd [Bsz*NTOK*Dsz];
__device__ float g_vd [Bsz*NTOK*Dsz];
__device__ float g_gate[Bsz*2];
__device__ bf16  g_wq  [Dsz*Dsz];
__device__ bf16  g_wout[Dsz*Dsz];
__device__ bf16  g_wka [Dsz*CRS];
__device__ bf16  g_wva [Dsz*CRS];
__device__ bf16  g_wkd [Dsz*CRS];
__device__ bf16  g_wvd [Dsz*CRS];

// ---------------- helpers ---------------------------------------------------
__device__ __forceinline__ uint32_t smem_u32(const void* p) {
    uint32_t a;
    asm("{ .reg .u64 t; cvta.to.shared.u64 t, %1; cvt.u32.u64 %0, t; }" : "=r"(a) : "l"(p));
    return a;
}
__device__ __forceinline__ void cp16(uint32_t dst, const void* src) {
    asm volatile("cp.async.cg.shared.global [%0], [%1], 16;" :: "r"(dst), "l"(src));
}
#define CP_COMMIT() asm volatile("cp.async.commit_group;" ::: "memory")

__device__ __forceinline__ uint32_t pack_bf2(float lo, float hi) {
    __nv_bfloat162 v = __floats2bfloat162_rn(lo, hi);
    return *(uint32_t*)&v;
}

// ---------------- bf16 mma.sync GEMM: C[m,n] = sum_k A[m,k]*W[n,k] ----------
// BM=BN=128, BK=64 elems. 8 warps (2x4), warp tile 64x32. Double-buffered.
#define LDE 72                         // padded bf16 elems per smem row (144B)
#define TILE_E (128*LDE)               // 9216 elems per tile
#define STAGE_E (2*TILE_E)             // A+B
#define GEMM_SMEM (2*STAGE_E*2)        // 73728 bytes (2 stages)

__device__ __forceinline__ void mma16(float* d, const uint32_t* a, const uint32_t* b) {
    asm volatile(
        "mma.sync.aligned.m16n8k16.row.col.f32.bf16.bf16.f32 "
        "{%0,%1,%2,%3}, {%4,%5,%6,%7}, {%8,%9}, {%0,%1,%2,%3};"
        : "+f"(d[0]), "+f"(d[1]), "+f"(d[2]), "+f"(d[3])
        : "r"(a[0]), "r"(a[1]), "r"(a[2]), "r"(a[3]), "r"(b[0]), "r"(b[1]));
}

__global__ __launch_bounds__(256, 2)
void gemm_bf(const bf16* __restrict__ A, const bf16* __restrict__ W,
             float* __restrict__ C, int M, int N, int K,
             const float* __restrict__ bias, const float* __restrict__ res) {
    extern __shared__ bf16 sm[];
    const int t = threadIdx.x;
    const int lane = t & 31, wid = t >> 5;
    const int warp_m = wid >> 2, warp_n = wid & 3;
    const int bm = blockIdx.y * 128, bn = blockIdx.x * 128;
    const int NIT = K / 64;
    const uint32_t sbase = smem_u32(sm);

    float acc[4][4][4];
    #pragma unroll
    for (int i = 0; i < 4; i++)
        #pragma unroll
        for (int j = 0; j < 4; j++)
            #pragma unroll
            for (int r = 0; r < 4; r++) acc[i][j][r] = 0.f;

    // stage load: A rows bm..+127, W rows bn..+127, k-cols IT*64..+63
    #define LOAD_STAGE(IT, S) do {                                             \
        const bf16* Ab = A + (long)bm * K + (IT) * 64;                         \
        const bf16* Wb = W + (long)bn * K + (IT) * 64;                         \
        uint32_t dA = sbase + (S) * (STAGE_E * 2);                             \
        uint32_t dB = dA + TILE_E * 2;                                         \
        _Pragma("unroll")                                                      \
        for (int i = 0; i < 4; i++) {                                          \
            int idx = i * 256 + t; int row = idx >> 3, g = idx & 7;            \
            cp16(dA + row * (LDE*2) + g * 16, Ab + (long)row * K + g * 8);     \
        }                                                                      \
        _Pragma("unroll")                                                      \
        for (int i = 0; i < 4; i++) {                                          \
            int idx = i * 256 + t; int row = idx >> 3, g = idx & 7;            \
            cp16(dB + row * (LDE*2) + g * 16, Wb + (long)row * K + g * 8);     \
        }                                                                      \
        CP_COMMIT();                                                           \
    } while (0)

    LOAD_STAGE(0, 0);

    for (int it = 0; it < NIT; it++) {
        int s = it & 1;
        if (it + 1 < NIT) {
            LOAD_STAGE(it + 1, (it + 1) & 1);
            asm volatile("cp.async.wait_group 1;" ::: "memory");
        } else {
            asm volatile("cp.async.wait_group 0;" ::: "memory");
        }
        __syncthreads();

        const bf16* As = sm + s * STAGE_E;
        const bf16* Bs = As + TILE_E;
        const int r = lane >> 2;
        #pragma unroll
        for (int ks = 0; ks < 4; ks++) {
            const int c0 = ks * 16 + 2 * (lane & 3);   // element offset
            uint32_t a[4][4], b[4][2];
            #pragma unroll
            for (int mt = 0; mt < 4; mt++) {
                int row = warp_m * 64 + mt * 16 + r;
                a[mt][0] = *(const uint32_t*)&As[row * LDE + c0];
                a[mt][1] = *(const uint32_t*)&As[(row + 8) * LDE + c0];
                a[mt][2] = *(const uint32_t*)&As[row * LDE + c0 + 8];
                a[mt][3] = *(const uint32_t*)&As[(row + 8) * LDE + c0 + 8];
            }
            #pragma unroll
            for (int nt = 0; nt < 4; nt++) {
                int rowb = warp_n * 32 + nt * 8 + r;
                b[nt][0] = *(const uint32_t*)&Bs[rowb * LDE + c0];
                b[nt][1] = *(const uint32_t*)&Bs[rowb * LDE + c0 + 8];
            }
            #pragma unroll
            for (int mt = 0; mt < 4; mt++)
                #pragma unroll
                for (int nt = 0; nt < 4; nt++)
                    mma16(acc[mt][nt], a[mt], b[nt]);
        }
        __syncthreads();
    }

    // ---- epilogue (fp32, optional bias + residual)
    #pragma unroll
    for (int mt = 0; mt < 4; mt++) {
        #pragma unroll
        for (int nt = 0; nt < 4; nt++) {
            int row = bm + warp_m * 64 + mt * 16 + (lane >> 2);
            int col = bn + warp_n * 32 + nt * 8 + 2 * (lane & 3);
            float2 v0 = make_float2(acc[mt][nt][0], acc[mt][nt][1]);
            float2 v1 = make_float2(acc[mt][nt][2], acc[mt][nt][3]);
            if (bias) {
                float2 bb = *(const float2*)(bias + col);
                v0.x += bb.x; v0.y += bb.y; v1.x += bb.x; v1.y += bb.y;
            }
            if (res) {
                float2 r0 = *(const float2*)(res + (long)row * N + col);
                float2 r1 = *(const float2*)(res + (long)(row + 8) * N + col);
                v0.x += r0.x; v0.y += r0.y; v1.x += r1.x; v1.y += r1.y;
            }
            *(float2*)(C + (long)row * N + col) = v0;
            *(float2*)(C + (long)(row + 8) * N + col) = v1;
        }
    }
}

// ---------------- fp32 -> bf16 conversion ------------------------------------
__global__ void f2bf(const float* __restrict__ x, bf16* __restrict__ y, int n4) {
    int i = blockIdx.x * blockDim.x + threadIdx.x;
    if (i >= n4) return;
    float4 v = ((const float4*)x)[i];
    uint2 o;
    o.x = pack_bf2(v.x, v.y);
    o.y = pack_bf2(v.z, v.w);
    ((uint2*)y)[i] = o;
}

// ---------------- gather encoder tokens (bf16) ------------------------------
__global__ void gather_tokens(const float* __restrict__ enc) {
    int i = blockIdx.x * blockDim.x + threadIdx.x;
    if (i >= Bsz*NTOK*CRS) return;
    int c = i % CRS;
    int tt = (i / CRS) % NTOK;
    int b = i / (CRS*NTOK);
    g_dis [i] = __float2bfloat16_rn(enc[((long)b*ETOK + tt)        * CRS + c]);
    g_anat[i] = __float2bfloat16_rn(enc[((long)b*ETOK + NTOK + tt) * CRS + c]);
}

// ---------------- per-batch gate scalars -----------------------------------
__global__ void gate_kernel(const float* __restrict__ w_gate,
                            const float* __restrict__ b_gate,
                            const float* __restrict__ anat_logit,
                            const float* __restrict__ dis_logit) {
    int b = blockIdx.x;
    __shared__ float red[256];
    float partial = 0.f;
    for (int c = threadIdx.x; c < CRS; c += 256) {
        float s = 0.f;
        #pragma unroll
        for (int t = 0; t < NTOK; t++)
            s += __bfloat162float(g_dis[(b*NTOK + t)*CRS + c]);
        partial += (s * (1.0f/NTOK)) * w_gate[c];
    }
    red[threadIdx.x] = partial;
    __syncthreads();
    for (int off = 128; off > 0; off >>= 1) {
        if (threadIdx.x < off) red[threadIdx.x] += red[threadIdx.x + off];
        __syncthreads();
    }
    if (threadIdx.x == 0) {
        float shift = red[0] + b_gate[0];
        g_gate[b*2+0] = 1.0f / (1.0f + expf(-(anat_logit[0] - shift)));
        g_gate[b*2+1] = 1.0f / (1.0f + expf(-(dis_logit[0]  + shift)));
    }
}

// ---------------- fused dual attention + gating (fp32 math, bf16 z out) -----
__global__ __launch_bounds__(128)
void attn_kernel() {
    __shared__ float ka[NTOK][HD], va[NTOK][HD], kd[NTOK][HD], vd[NTOK][HD];
    const int b = blockIdx.z, h = blockIdx.y;
    const int s = blockIdx.x * 128 + threadIdx.x;

    for (int i = threadIdx.x; i < NTOK*HD; i += 128) {
        int t = i / HD, d = i % HD;
        long src = (long)(b*NTOK + t) * Dsz + h*HD + d;
        ka[t][d] = g_ka[src];  va[t][d] = g_va[src];
        kd[t][d] = g_kd[src];  vd[t][d] = g_vd[src];
    }
    __syncthreads();

    const float ga = g_gate[b*2+0];
    const float gd = g_gate[b*2+1];

    float q[HD];
    const float* qp = g_q + ((long)(b*Ssz + s)) * Dsz + h*HD;
    #pragma unroll
    for (int d = 0; d < HD; d += 4) {
        float4 v = *(const float4*)(qp + d);
        q[d] = v.x; q[d+1] = v.y; q[d+2] = v.z; q[d+3] = v.w;
    }

    float out[HD];
    #pragma unroll
    for (int d = 0; d < HD; d++) out[d] = 0.f;
    float sc[NTOK];

    float mx = -1e30f;
    #pragma unroll
    for (int j = 0; j < NTOK; j++) {
        float s2 = 0.f;
        #pragma unroll
        for (int d = 0; d < HD; d++) s2 = fmaf(q[d], ka[j][d], s2);
        sc[j] = s2 * SCALE;  mx = fmaxf(mx, sc[j]);
    }
    float sum = 0.f;
    #pragma unroll
    for (int j = 0; j < NTOK; j++) { sc[j] = expf(sc[j] - mx); sum += sc[j]; }
    float inv = ga / sum;
    #pragma unroll
    for (int j = 0; j < NTOK; j++) {
        float p = sc[j] * inv;
        #pragma unroll
        for (int d = 0; d < HD; d++) out[d] = fmaf(p, va[j][d], out[d]);
    }

    mx = -1e30f;
    #pragma unroll
    for (int j = 0; j < NTOK; j++) {
        float s2 = 0.f;
        #pragma unroll
        for (int d = 0; d < HD; d++) s2 = fmaf(q[d], kd[j][d], s2);
        sc[j] = s2 * SCALE;  mx = fmaxf(mx, sc[j]);
    }
    sum = 0.f;
    #pragma unroll
    for (int j = 0; j < NTOK; j++) { sc[j] = expf(sc[j] - mx); sum += sc[j]; }
    inv = gd / sum;
    #pragma unroll
    for (int j = 0; j < NTOK; j++) {
        float p = sc[j] * inv;
        #pragma unroll
        for (int d = 0; d < HD; d++) out[d] = fmaf(p, vd[j][d], out[d]);
    }

    bf16* zp = g_z + ((long)(b*Ssz + s)) * Dsz + h*HD;
    #pragma unroll
    for (int d = 0; d < HD; d += 8) {
        uint4 o;
        o.x = pack_bf2(out[d],   out[d+1]);
        o.y = pack_bf2(out[d+2], out[d+3]);
        o.z = pack_bf2(out[d+4], out[d+5]);
        o.w = pack_bf2(out[d+6], out[d+7]);
        *(uint4*)(zp + d) = o;
    }
}

// ---------------- launch ----------------------------------------------------
extern "C" void kernel_launch(void* const* d_in, const int* in_sizes, int n_in,
                              void* d_out, int out_size) {
    const float* hidden  = (const float*)d_in[0];
    const float* enc     = (const float*)d_in[1];
    const float* w_q     = (const float*)d_in[2];
    const float* w_k     = (const float*)d_in[3];
    const float* w_v     = (const float*)d_in[4];
    const float* w_k_dis = (const float*)d_in[5];
    const float* w_v_dis = (const float*)d_in[6];
    const float* w_gate  = (const float*)d_in[7];
    const float* b_gate  = (const float*)d_in[8];
    const float* a_logit = (const float*)d_in[9];
    const float* d_logit = (const float*)d_in[10];
    const float* w_out   = (const float*)d_in[11];
    const float* b_out   = (const float*)d_in[12];
    float* out = (float*)d_out;

    bf16 *anat_p, *dis_p, *z_p, *hidb_p, *wq_p, *wout_p, *wka_p, *wva_p, *wkd_p, *wvd_p;
    float *ka_p, *va_p, *kd_p, *vd_p, *q_p;
    cudaGetSymbolAddress((void**)&anat_p, g_anat);
    cudaGetSymbolAddress((void**)&dis_p,  g_dis);
    cudaGetSymbolAddress((void**)&ka_p,   g_ka);
    cudaGetSymbolAddress((void**)&va_p,   g_va);
    cudaGetSymbolAddress((void**)&kd_p,   g_kd);
    cudaGetSymbolAddress((void**)&vd_p,   g_vd);
    cudaGetSymbolAddress((void**)&q_p,    g_q);
    cudaGetSymbolAddress((void**)&z_p,    g_z);
    cudaGetSymbolAddress((void**)&hidb_p, g_hidb);
    cudaGetSymbolAddress((void**)&wq_p,   g_wq);
    cudaGetSymbolAddress((void**)&wout_p, g_wout);
    cudaGetSymbolAddress((void**)&wka_p,  g_wka);
    cudaGetSymbolAddress((void**)&wva_p,  g_wva);
    cudaGetSymbolAddress((void**)&wkd_p,  g_wkd);
    cudaGetSymbolAddress((void**)&wvd_p,  g_wvd);

    cudaFuncSetAttribute(gemm_bf, cudaFuncAttributeMaxDynamicSharedMemorySize, GEMM_SMEM);

    // fp32 -> bf16 conversion prepass
    {
        int n4 = MS*Dsz/4;
        f2bf<<<(n4 + 255)/256, 256>>>(hidden, hidb_p, n4);
        int w4 = Dsz*Dsz/4;
        f2bf<<<(w4 + 255)/256, 256>>>(w_q,   wq_p,   w4);
        f2bf<<<(w4 + 255)/256, 256>>>(w_out, wout_p, w4);
        int k4 = Dsz*CRS/4;
        f2bf<<<(k4 + 255)/256, 256>>>(w_k,     wka_p, k4);
        f2bf<<<(k4 + 255)/256, 256>>>(w_v,     wva_p, k4);
        f2bf<<<(k4 + 255)/256, 256>>>(w_k_dis, wkd_p, k4);
        f2bf<<<(k4 + 255)/256, 256>>>(w_v_dis, wvd_p, k4);
    }
    { int n = Bsz*NTOK*CRS; gather_tokens<<<(n + 255)/256, 256>>>(enc); }
    gate_kernel<<<Bsz, 256>>>(w_gate, b_gate, a_logit, d_logit);

    // KV projections: M=512, N=1280, K=768
    {
        dim3 grid(Dsz/128, (Bsz*NTOK)/128);
        gemm_bf<<<grid, 256, GEMM_SMEM>>>(anat_p, wka_p, ka_p, Bsz*NTOK, Dsz, CRS, nullptr, nullptr);
        gemm_bf<<<grid, 256, GEMM_SMEM>>>(anat_p, wva_p, va_p, Bsz*NTOK, Dsz, CRS, nullptr, nullptr);
        gemm_bf<<<grid, 256, GEMM_SMEM>>>(dis_p,  wkd_p, kd_p, Bsz*NTOK, Dsz, CRS, nullptr, nullptr);
        gemm_bf<<<grid, 256, GEMM_SMEM>>>(dis_p,  wvd_p, vd_p, Bsz*NTOK, Dsz, CRS, nullptr, nullptr);
    }
    // Q projection: M=32768, N=1280, K=1280 (fp32 out)
    {
        dim3 grid(Dsz/128, MS/128);
        gemm_bf<<<grid, 256, GEMM_SMEM>>>(hidb_p, wq_p, q_p, MS, Dsz, Dsz, nullptr, nullptr);
    }
    // attention + gating
    {
        dim3 grid(Ssz/128, HEADS, Bsz);
        attn_kernel<<<grid, 128>>>();
    }
    // out projection + bias + residual
    {
        dim3 grid(Dsz/128, MS/128);
        gemm_bf<<<grid, 256, GEMM_SMEM>>>(z_p, wout_p, out, MS, Dsz, Dsz, b_out, hidden);
    }
}

// round 6
// speedup vs baseline: 5.9344x; 1.0913x over previous
#include <cuda_runtime.h>
#include <cuda_bf16.h>
#include <math.h>
#include <stdint.h>

#define Bsz   32
#define Ssz   1024
#define Dsz   1280
#define CRS   768
#define HEADS 20
#define HD    64
#define NTOK  16
#define ETOK  48
#define MS    (Bsz*Ssz)
#define SCALE 0.125f

typedef __nv_bfloat16 bf16;

// ---------------- scratch (device globals: allocation-free) ----------------
__device__ float g_q  [MS*Dsz];            // fp32 Q (precision)
__device__ bf16  g_z  [MS*Dsz];            // bf16 attention output
__device__ bf16  g_hidb[MS*Dsz];           // bf16 hidden
__device__ bf16  g_anat[Bsz*NTOK*CRS];
__device__ bf16  g_dis [Bsz*NTOK*CRS];
__device__ float g_ka [Bsz*NTOK*Dsz];
__device__ float g_va [Bsz*NTOK*Dsz];
__device__ float g_kd [Bsz*NTOK*Dsz];
__device__ float g_vd [Bsz*NTOK*Dsz];
__device__ float g_gate[Bsz*2];
__device__ bf16  g_wq  [Dsz*Dsz];
__device__ bf16  g_wout[Dsz*Dsz];
__device__ bf16  g_wka [Dsz*CRS];
__device__ bf16  g_wva [Dsz*CRS];
__device__ bf16  g_wkd [Dsz*CRS];
__device__ bf16  g_wvd [Dsz*CRS];

// ---------------- helpers ---------------------------------------------------
__device__ __forceinline__ uint32_t smem_u32(const void* p) {
    uint32_t a;
    asm("{ .reg .u64 t; cvta.to.shared.u64 t, %1; cvt.u32.u64 %0, t; }" : "=r"(a) : "l"(p));
    return a;
}
__device__ __forceinline__ void cp16(uint32_t dst, const void* src) {
    asm volatile("cp.async.cg.shared.global [%0], [%1], 16;" :: "r"(dst), "l"(src));
}
#define CP_COMMIT() asm volatile("cp.async.commit_group;" ::: "memory")

__device__ __forceinline__ uint32_t pack_bf2(float lo, float hi) {
    __nv_bfloat162 v = __floats2bfloat162_rn(lo, hi);
    return *(uint32_t*)&v;
}
__device__ __forceinline__ void ldsm4(uint32_t* r, uint32_t addr) {
    asm volatile("ldmatrix.sync.aligned.m8n8.x4.shared.b16 {%0,%1,%2,%3}, [%4];"
                 : "=r"(r[0]), "=r"(r[1]), "=r"(r[2]), "=r"(r[3]) : "r"(addr));
}
__device__ __forceinline__ void mma16(float* d, const uint32_t* a, const uint32_t* b) {
    asm volatile(
        "mma.sync.aligned.m16n8k16.row.col.f32.bf16.bf16.f32 "
        "{%0,%1,%2,%3}, {%4,%5,%6,%7}, {%8,%9}, {%0,%1,%2,%3};"
        : "+f"(d[0]), "+f"(d[1]), "+f"(d[2]), "+f"(d[3])
        : "r"(a[0]), "r"(a[1]), "r"(a[2]), "r"(a[3]), "r"(b[0]), "r"(b[1]));
}

// ---------------- bf16 mma.sync GEMM (ldmatrix fragments, batched) ----------
// BM=BN=128, BK=64 elems. 8 warps (2x4), warp tile 64x32. Double-buffered.
#define LDE 72                         // padded bf16 elems per smem row (144B)
#define TILE_E (128*LDE)
#define TILE_BYTES (TILE_E*2)          // 18432
#define STAGE_BYTES (2*TILE_BYTES)     // 36864
#define GEMM_SMEM (2*STAGE_BYTES)      // 73728

struct GemmBatch {
    const bf16* A[4];
    const bf16* W[4];
    float*      C[4];
};

__global__ __launch_bounds__(256, 2)
void gemm_bf(GemmBatch gb, int M, int N, int K,
             const float* __restrict__ bias, const float* __restrict__ res) {
    extern __shared__ bf16 sm[];
    const int t = threadIdx.x;
    const int lane = t & 31, wid = t >> 5;
    const int warp_m = wid >> 2, warp_n = wid & 3;
    const int bm = blockIdx.y * 128, bn = blockIdx.x * 128;
    const int NIT = K / 64;
    const uint32_t sbase = smem_u32(sm);

    const bf16* __restrict__ A = gb.A[blockIdx.z];
    const bf16* __restrict__ W = gb.W[blockIdx.z];
    float* __restrict__ C      = gb.C[blockIdx.z];

    // ldmatrix per-lane byte offsets within a stage
    const uint32_t aLane = ((uint32_t)(warp_m*64 + (lane & 15)) * LDE
                          + ((lane >> 4) << 3)) * 2;
    const uint32_t bLane = ((uint32_t)(warp_n*32 + ((lane >> 4) << 3) + (lane & 7)) * LDE
                          + (((lane >> 3) & 1) << 3)) * 2;

    float acc[4][4][4];
    #pragma unroll
    for (int i = 0; i < 4; i++)
        #pragma unroll
        for (int j = 0; j < 4; j++)
            #pragma unroll
            for (int r = 0; r < 4; r++) acc[i][j][r] = 0.f;

    #define LOAD_STAGE(IT, S) do {                                             \
        const bf16* Ab = A + (long)bm * K + (IT) * 64;                         \
        const bf16* Wb = W + (long)bn * K + (IT) * 64;                         \
        uint32_t dA = sbase + (S) * STAGE_BYTES;                               \
        uint32_t dB = dA + TILE_BYTES;                                         \
        _Pragma("unroll")                                                      \
        for (int i = 0; i < 4; i++) {                                          \
            int idx = i * 256 + t; int row = idx >> 3, g = idx & 7;            \
            cp16(dA + row * (LDE*2) + g * 16, Ab + (long)row * K + g * 8);     \
        }                                                                      \
        _Pragma("unroll")                                                      \
        for (int i = 0; i < 4; i++) {                                          \
            int idx = i * 256 + t; int row = idx >> 3, g = idx & 7;            \
            cp16(dB + row * (LDE*2) + g * 16, Wb + (long)row * K + g * 8);     \
        }                                                                      \
        CP_COMMIT();                                                           \
    } while (0)

    LOAD_STAGE(0, 0);

    for (int it = 0; it < NIT; it++) {
        int s = it & 1;
        if (it + 1 < NIT) {
            LOAD_STAGE(it + 1, s ^ 1);
            asm volatile("cp.async.wait_group 1;" ::: "memory");
        } else {
            asm volatile("cp.async.wait_group 0;" ::: "memory");
        }
        __syncthreads();

        const uint32_t aBase = sbase + s * STAGE_BYTES + aLane;
        const uint32_t bBase = sbase + s * STAGE_BYTES + TILE_BYTES + bLane;
        #pragma unroll
        for (int ks = 0; ks < 4; ks++) {
            uint32_t a[4][4], bb[2][4];
            #pragma unroll
            for (int mt = 0; mt < 4; mt++)
                ldsm4(a[mt], aBase + mt * (16*LDE*2) + ks * 32);
            #pragma unroll
            for (int j = 0; j < 2; j++)
                ldsm4(bb[j], bBase + j * (16*LDE*2) + ks * 32);
            #pragma unroll
            for (int mt = 0; mt < 4; mt++)
                #pragma unroll
                for (int nt = 0; nt < 4; nt++)
                    mma16(acc[mt][nt], a[mt], &bb[nt >> 1][(nt & 1) * 2]);
        }
        __syncthreads();
    }

    // ---- epilogue (fp32, optional bias + residual)
    #pragma unroll
    for (int mt = 0; mt < 4; mt++) {
        #pragma unroll
        for (int nt = 0; nt < 4; nt++) {
            int row = bm + warp_m * 64 + mt * 16 + (lane >> 2);
            int col = bn + warp_n * 32 + nt * 8 + 2 * (lane & 3);
            float2 v0 = make_float2(acc[mt][nt][0], acc[mt][nt][1]);
            float2 v1 = make_float2(acc[mt][nt][2], acc[mt][nt][3]);
            if (bias) {
                float2 bb = *(const float2*)(bias + col);
                v0.x += bb.x; v0.y += bb.y; v1.x += bb.x; v1.y += bb.y;
            }
            if (res) {
                float2 r0 = *(const float2*)(res + (long)row * N + col);
                float2 r1 = *(const float2*)(res + (long)(row + 8) * N + col);
                v0.x += r0.x; v0.y += r0.y; v1.x += r1.x; v1.y += r1.y;
            }
            *(float2*)(C + (long)row * N + col) = v0;
            *(float2*)(C + (long)(row + 8) * N + col) = v1;
        }
    }
}

// ---------------- fp32 -> bf16 conversion ------------------------------------
__global__ void f2bf(const float* __restrict__ x, bf16* __restrict__ y, int n4) {
    int i = blockIdx.x * blockDim.x + threadIdx.x;
    if (i >= n4) return;
    float4 v = ((const float4*)x)[i];
    uint2 o;
    o.x = pack_bf2(v.x, v.y);
    o.y = pack_bf2(v.z, v.w);
    ((uint2*)y)[i] = o;
}

struct ConvBatch { const float* src[6]; bf16* dst[6]; int n4[6]; };
__global__ void f2bf_batch(ConvBatch cb) {
    int seg = blockIdx.y;
    int i = blockIdx.x * blockDim.x + threadIdx.x;
    if (i >= cb.n4[seg]) return;
    float4 v = ((const float4*)cb.src[seg])[i];
    uint2 o;
    o.x = pack_bf2(v.x, v.y);
    o.y = pack_bf2(v.z, v.w);
    ((uint2*)cb.dst[seg])[i] = o;
}

// ---------------- gather encoder tokens (bf16) ------------------------------
__global__ void gather_tokens(const float* __restrict__ enc) {
    int i = blockIdx.x * blockDim.x + threadIdx.x;
    if (i >= Bsz*NTOK*CRS) return;
    int c = i % CRS;
    int tt = (i / CRS) % NTOK;
    int b = i / (CRS*NTOK);
    g_dis [i] = __float2bfloat16_rn(enc[((long)b*ETOK + tt)        * CRS + c]);
    g_anat[i] = __float2bfloat16_rn(enc[((long)b*ETOK + NTOK + tt) * CRS + c]);
}

// ---------------- per-batch gate scalars -----------------------------------
__global__ void gate_kernel(const float* __restrict__ w_gate,
                            const float* __restrict__ b_gate,
                            const float* __restrict__ anat_logit,
                            const float* __restrict__ dis_logit) {
    int b = blockIdx.x;
    __shared__ float red[256];
    float partial = 0.f;
    for (int c = threadIdx.x; c < CRS; c += 256) {
        float s = 0.f;
        #pragma unroll
        for (int t = 0; t < NTOK; t++)
            s += __bfloat162float(g_dis[(b*NTOK + t)*CRS + c]);
        partial += (s * (1.0f/NTOK)) * w_gate[c];
    }
    red[threadIdx.x] = partial;
    __syncthreads();
    for (int off = 128; off > 0; off >>= 1) {
        if (threadIdx.x < off) red[threadIdx.x] += red[threadIdx.x + off];
        __syncthreads();
    }
    if (threadIdx.x == 0) {
        float shift = red[0] + b_gate[0];
        g_gate[b*2+0] = 1.0f / (1.0f + expf(-(anat_logit[0] - shift)));
        g_gate[b*2+1] = 1.0f / (1.0f + expf(-(dis_logit[0]  + shift)));
    }
}

// ---------------- fused dual attention + gating (fp32 math, bf16 z out) -----
__global__ __launch_bounds__(128)
void attn_kernel() {
    __shared__ float ka[NTOK][HD], va[NTOK][HD], kd[NTOK][HD], vd[NTOK][HD];
    const int b = blockIdx.z, h = blockIdx.y;
    const int s = blockIdx.x * 128 + threadIdx.x;

    for (int i = threadIdx.x; i < NTOK*HD; i += 128) {
        int t = i / HD, d = i % HD;
        long src = (long)(b*NTOK + t) * Dsz + h*HD + d;
        ka[t][d] = g_ka[src];  va[t][d] = g_va[src];
        kd[t][d] = g_kd[src];  vd[t][d] = g_vd[src];
    }
    __syncthreads();

    const float ga = g_gate[b*2+0];
    const float gd = g_gate[b*2+1];

    float q[HD];
    const float* qp = g_q + ((long)(b*Ssz + s)) * Dsz + h*HD;
    #pragma unroll
    for (int d = 0; d < HD; d += 4) {
        float4 v = *(const float4*)(qp + d);
        q[d] = v.x; q[d+1] = v.y; q[d+2] = v.z; q[d+3] = v.w;
    }

    float out[HD];
    #pragma unroll
    for (int d = 0; d < HD; d++) out[d] = 0.f;
    float sc[NTOK];

    float mx = -1e30f;
    #pragma unroll
    for (int j = 0; j < NTOK; j++) {
        float s2 = 0.f;
        #pragma unroll
        for (int d = 0; d < HD; d++) s2 = fmaf(q[d], ka[j][d], s2);
        sc[j] = s2 * SCALE;  mx = fmaxf(mx, sc[j]);
    }
    float sum = 0.f;
    #pragma unroll
    for (int j = 0; j < NTOK; j++) { sc[j] = expf(sc[j] - mx); sum += sc[j]; }
    float inv = ga / sum;
    #pragma unroll
    for (int j = 0; j < NTOK; j++) {
        float p = sc[j] * inv;
        #pragma unroll
        for (int d = 0; d < HD; d++) out[d] = fmaf(p, va[j][d], out[d]);
    }

    mx = -1e30f;
    #pragma unroll
    for (int j = 0; j < NTOK; j++) {
        float s2 = 0.f;
        #pragma unroll
        for (int d = 0; d < HD; d++) s2 = fmaf(q[d], kd[j][d], s2);
        sc[j] = s2 * SCALE;  mx = fmaxf(mx, sc[j]);
    }
    sum = 0.f;
    #pragma unroll
    for (int j = 0; j < NTOK; j++) { sc[j] = expf(sc[j] - mx); sum += sc[j]; }
    inv = gd / sum;
    #pragma unroll
    for (int j = 0; j < NTOK; j++) {
        float p = sc[j] * inv;
        #pragma unroll
        for (int d = 0; d < HD; d++) out[d] = fmaf(p, vd[j][d], out[d]);
    }

    bf16* zp = g_z + ((long)(b*Ssz + s)) * Dsz + h*HD;
    #pragma unroll
    for (int d = 0; d < HD; d += 8) {
        uint4 o;
        o.x = pack_bf2(out[d],   out[d+1]);
        o.y = pack_bf2(out[d+2], out[d+3]);
        o.z = pack_bf2(out[d+4], out[d+5]);
        o.w = pack_bf2(out[d+6], out[d+7]);
        *(uint4*)(zp + d) = o;
    }
}

// ---------------- launch ----------------------------------------------------
extern "C" void kernel_launch(void* const* d_in, const int* in_sizes, int n_in,
                              void* d_out, int out_size) {
    const float* hidden  = (const float*)d_in[0];
    const float* enc     = (const float*)d_in[1];
    const float* w_q     = (const float*)d_in[2];
    const float* w_k     = (const float*)d_in[3];
    const float* w_v     = (const float*)d_in[4];
    const float* w_k_dis = (const float*)d_in[5];
    const float* w_v_dis = (const float*)d_in[6];
    const float* w_gate  = (const float*)d_in[7];
    const float* b_gate  = (const float*)d_in[8];
    const float* a_logit = (const float*)d_in[9];
    const float* d_logit = (const float*)d_in[10];
    const float* w_out   = (const float*)d_in[11];
    const float* b_out   = (const float*)d_in[12];
    float* out = (float*)d_out;

    bf16 *anat_p, *dis_p, *z_p, *hidb_p, *wq_p, *wout_p, *wka_p, *wva_p, *wkd_p, *wvd_p;
    float *ka_p, *va_p, *kd_p, *vd_p, *q_p;
    cudaGetSymbolAddress((void**)&anat_p, g_anat);
    cudaGetSymbolAddress((void**)&dis_p,  g_dis);
    cudaGetSymbolAddress((void**)&ka_p,   g_ka);
    cudaGetSymbolAddress((void**)&va_p,   g_va);
    cudaGetSymbolAddress((void**)&kd_p,   g_kd);
    cudaGetSymbolAddress((void**)&vd_p,   g_vd);
    cudaGetSymbolAddress((void**)&q_p,    g_q);
    cudaGetSymbolAddress((void**)&z_p,    g_z);
    cudaGetSymbolAddress((void**)&hidb_p, g_hidb);
    cudaGetSymbolAddress((void**)&wq_p,   g_wq);
    cudaGetSymbolAddress((void**)&wout_p, g_wout);
    cudaGetSymbolAddress((void**)&wka_p,  g_wka);
    cudaGetSymbolAddress((void**)&wva_p,  g_wva);
    cudaGetSymbolAddress((void**)&wkd_p,  g_wkd);
    cudaGetSymbolAddress((void**)&wvd_p,  g_wvd);

    cudaFuncSetAttribute(gemm_bf, cudaFuncAttributeMaxDynamicSharedMemorySize, GEMM_SMEM);

    // conversions: hidden (big) + 6 weights (batched single launch)
    {
        int n4 = MS*Dsz/4;
        f2bf<<<(n4 + 255)/256, 256>>>(hidden, hidb_p, n4);
        ConvBatch cb;
        int w4 = Dsz*Dsz/4, k4 = Dsz*CRS/4;
        cb.src[0] = w_q;     cb.dst[0] = wq_p;   cb.n4[0] = w4;
        cb.src[1] = w_out;   cb.dst[1] = wout_p; cb.n4[1] = w4;
        cb.src[2] = w_k;     cb.dst[2] = wka_p;  cb.n4[2] = k4;
        cb.src[3] = w_v;     cb.dst[3] = wva_p;  cb.n4[3] = k4;
        cb.src[4] = w_k_dis; cb.dst[4] = wkd_p;  cb.n4[4] = k4;
        cb.src[5] = w_v_dis; cb.dst[5] = wvd_p;  cb.n4[5] = k4;
        dim3 grid((w4 + 255)/256, 6);
        f2bf_batch<<<grid, 256>>>(cb);
    }
    { int n = Bsz*NTOK*CRS; gather_tokens<<<(n + 255)/256, 256>>>(enc); }
    gate_kernel<<<Bsz, 256>>>(w_gate, b_gate, a_logit, d_logit);

    // KV projections (batched): M=512, N=1280, K=768, z=4
    {
        GemmBatch gb;
        gb.A[0] = anat_p; gb.W[0] = wka_p; gb.C[0] = ka_p;
        gb.A[1] = anat_p; gb.W[1] = wva_p; gb.C[1] = va_p;
        gb.A[2] = dis_p;  gb.W[2] = wkd_p; gb.C[2] = kd_p;
        gb.A[3] = dis_p;  gb.W[3] = wvd_p; gb.C[3] = vd_p;
        dim3 grid(Dsz/128, (Bsz*NTOK)/128, 4);
        gemm_bf<<<grid, 256, GEMM_SMEM>>>(gb, Bsz*NTOK, Dsz, CRS, nullptr, nullptr);
    }
    // Q projection: M=32768, N=1280, K=1280 (fp32 out)
    {
        GemmBatch gb;
        gb.A[0] = hidb_p; gb.W[0] = wq_p; gb.C[0] = q_p;
        gb.A[1] = gb.A[0]; gb.W[1] = gb.W[0]; gb.C[1] = gb.C[0];
        gb.A[2] = gb.A[0]; gb.W[2] = gb.W[0]; gb.C[2] = gb.C[0];
        gb.A[3] = gb.A[0]; gb.W[3] = gb.W[0]; gb.C[3] = gb.C[0];
        dim3 grid(Dsz/128, MS/128, 1);
        gemm_bf<<<grid, 256, GEMM_SMEM>>>(gb, MS, Dsz, Dsz, nullptr, nullptr);
    }
    // attention + gating
    {
        dim3 grid(Ssz/128, HEADS, Bsz);
        attn_kernel<<<grid, 128>>>();
    }
    // out projection + bias + residual
    {
        GemmBatch gb;
        gb.A[0] = z_p; gb.W[0] = wout_p; gb.C[0] = out;
        gb.A[1] = gb.A[0]; gb.W[1] = gb.W[0]; gb.C[1] = gb.C[0];
        gb.A[2] = gb.A[0]; gb.W[2] = gb.W[0]; gb.C[2] = gb.C[0];
        gb.A[3] = gb.A[0]; gb.W[3] = gb.W[0]; gb.C[3] = gb.C[0];
        dim3 grid(Dsz/128, MS/128, 1);
        gemm_bf<<<grid, 256, GEMM_SMEM>>>(gb, MS, Dsz, Dsz, b_out, hidden);
    }
}

// round 7
// speedup vs baseline: 6.0988x; 1.0277x over previous
#include <cuda_runtime.h>
#include <cuda_bf16.h>
#include <math.h>
#include <stdint.h>

#define Bsz   32
#define Ssz   1024
#define Dsz   1280
#define CRS   768
#define HEADS 20
#define HD    64
#define NTOK  16
#define ETOK  48
#define MS    (Bsz*Ssz)
#define SCALE 0.125f

typedef __nv_bfloat16 bf16;

// ---------------- scratch (device globals: allocation-free) ----------------
__device__ float g_q  [MS*Dsz];            // fp32 Q (precision)
__device__ bf16  g_z  [MS*Dsz];            // bf16 attention output
__device__ bf16  g_hidb[MS*Dsz];           // bf16 hidden
__device__ bf16  g_anat[Bsz*NTOK*CRS];
__device__ bf16  g_dis [Bsz*NTOK*CRS];
__device__ float g_ka [Bsz*NTOK*Dsz];
__device__ float g_va [Bsz*NTOK*Dsz];
__device__ float g_kd [Bsz*NTOK*Dsz];
__device__ float g_vd [Bsz*NTOK*Dsz];
__device__ float g_gate[Bsz*2];
__device__ bf16  g_wq  [Dsz*Dsz];
__device__ bf16  g_wout[Dsz*Dsz];
__device__ bf16  g_wka [Dsz*CRS];
__device__ bf16  g_wva [Dsz*CRS];
__device__ bf16  g_wkd [Dsz*CRS];
__device__ bf16  g_wvd [Dsz*CRS];

// ---------------- helpers ---------------------------------------------------
__device__ __forceinline__ uint32_t smem_u32(const void* p) {
    uint32_t a;
    asm("{ .reg .u64 t; cvta.to.shared.u64 t, %1; cvt.u32.u64 %0, t; }" : "=r"(a) : "l"(p));
    return a;
}
__device__ __forceinline__ void cp16(uint32_t dst, const void* src) {
    asm volatile("cp.async.cg.shared.global [%0], [%1], 16;" :: "r"(dst), "l"(src));
}
#define CP_COMMIT() asm volatile("cp.async.commit_group;" ::: "memory")
#define CP_WAIT0()  asm volatile("cp.async.wait_group 0;" ::: "memory")

__device__ __forceinline__ uint32_t pack_bf2(float lo, float hi) {
    __nv_bfloat162 v = __floats2bfloat162_rn(lo, hi);
    return *(uint32_t*)&v;
}
__device__ __forceinline__ void ldsm4(uint32_t* r, uint32_t addr) {
    asm volatile("ldmatrix.sync.aligned.m8n8.x4.shared.b16 {%0,%1,%2,%3}, [%4];"
                 : "=r"(r[0]), "=r"(r[1]), "=r"(r[2]), "=r"(r[3]) : "r"(addr));
}
__device__ __forceinline__ void mma16(float* d, const uint32_t* a, const uint32_t* b) {
    asm volatile(
        "mma.sync.aligned.m16n8k16.row.col.f32.bf16.bf16.f32 "
        "{%0,%1,%2,%3}, {%4,%5,%6,%7}, {%8,%9}, {%0,%1,%2,%3};"
        : "+f"(d[0]), "+f"(d[1]), "+f"(d[2]), "+f"(d[3])
        : "r"(a[0]), "r"(a[1]), "r"(a[2]), "r"(a[3]), "r"(b[0]), "r"(b[1]));
}

// ---------------- bf16 mma.sync GEMM (single-sync pipeline) -----------------
// BM=BN=128, BK=64. 8 warps (2x4), warp tile 64x32. Double-buffered cp.async.
#define LDE 72                         // padded bf16 elems per smem row (144B)
#define TILE_E (128*LDE)
#define TILE_BYTES (TILE_E*2)          // 18432
#define STAGE_BYTES (2*TILE_BYTES)     // 36864
#define GEMM_SMEM (2*STAGE_BYTES)      // 73728

// entry 0: Q proj (M rows via blockIdx.y<256); entries 1..4: KV projections.
struct ProjBatch {
    const bf16* A[5];
    const bf16* W[5];
    float*      C[5];
    int         K[5];
};

__device__ __forceinline__ void gemm_core(
    const bf16* __restrict__ A, const bf16* __restrict__ W,
    float* __restrict__ C, int N, int K, int bm, int bn,
    const float* __restrict__ bias, const float* __restrict__ res,
    bf16* sm, uint32_t sbase, int t, int lane, int warp_m, int warp_n)
{
    const int NIT = K / 64;

    const uint32_t aLane = ((uint32_t)(warp_m*64 + (lane & 15)) * LDE
                          + ((lane >> 4) << 3)) * 2;
    const uint32_t bLane = ((uint32_t)(warp_n*32 + ((lane >> 4) << 3) + (lane & 7)) * LDE
                          + (((lane >> 3) & 1) << 3)) * 2;

    float acc[4][4][4];
    #pragma unroll
    for (int i = 0; i < 4; i++)
        #pragma unroll
        for (int j = 0; j < 4; j++)
            #pragma unroll
            for (int r = 0; r < 4; r++) acc[i][j][r] = 0.f;

    #define LOAD_STAGE(IT, S) do {                                             \
        const bf16* Ab = A + (long)bm * K + (IT) * 64;                         \
        const bf16* Wb = W + (long)bn * K + (IT) * 64;                         \
        uint32_t dA = sbase + (S) * STAGE_BYTES;                               \
        uint32_t dB = dA + TILE_BYTES;                                         \
        _Pragma("unroll")                                                      \
        for (int i = 0; i < 4; i++) {                                          \
            int idx = i * 256 + t; int row = idx >> 3, g = idx & 7;            \
            cp16(dA + row * (LDE*2) + g * 16, Ab + (long)row * K + g * 8);     \
        }                                                                      \
        _Pragma("unroll")                                                      \
        for (int i = 0; i < 4; i++) {                                          \
            int idx = i * 256 + t; int row = idx >> 3, g = idx & 7;            \
            cp16(dB + row * (LDE*2) + g * 16, Wb + (long)row * K + g * 8);     \
        }                                                                      \
        CP_COMMIT();                                                           \
    } while (0)

    LOAD_STAGE(0, 0);

    for (int it = 0; it < NIT; it++) {
        int s = it & 1;
        CP_WAIT0();                    // stage `it` data resident (this thread)
        __syncthreads();               // all threads done computing it-1 + data visible
        if (it + 1 < NIT)
            LOAD_STAGE(it + 1, s ^ 1); // flows during compute below

        const uint32_t aBase = sbase + s * STAGE_BYTES + aLane;
        const uint32_t bBase = sbase + s * STAGE_BYTES + TILE_BYTES + bLane;
        #pragma unroll
        for (int ks = 0; ks < 4; ks++) {
            uint32_t a[4][4], bb[2][4];
            #pragma unroll
            for (int mt = 0; mt < 4; mt++)
                ldsm4(a[mt], aBase + mt * (16*LDE*2) + ks * 32);
            #pragma unroll
            for (int j = 0; j < 2; j++)
                ldsm4(bb[j], bBase + j * (16*LDE*2) + ks * 32);
            #pragma unroll
            for (int mt = 0; mt < 4; mt++)
                #pragma unroll
                for (int nt = 0; nt < 4; nt++)
                    mma16(acc[mt][nt], a[mt], &bb[nt >> 1][(nt & 1) * 2]);
        }
    }

    // ---- epilogue (fp32, optional bias + residual)
    #pragma unroll
    for (int mt = 0; mt < 4; mt++) {
        #pragma unroll
        for (int nt = 0; nt < 4; nt++) {
            int row = bm + warp_m * 64 + mt * 16 + (lane >> 2);
            int col = bn + warp_n * 32 + nt * 8 + 2 * (lane & 3);
            float2 v0 = make_float2(acc[mt][nt][0], acc[mt][nt][1]);
            float2 v1 = make_float2(acc[mt][nt][2], acc[mt][nt][3]);
            if (bias) {
                float2 bb = *(const float2*)(bias + col);
                v0.x += bb.x; v0.y += bb.y; v1.x += bb.x; v1.y += bb.y;
            }
            if (res) {
                float2 r0 = *(const float2*)(res + (long)row * N + col);
                float2 r1 = *(const float2*)(res + (long)(row + 8) * N + col);
                v0.x += r0.x; v0.y += r0.y; v1.x += r1.x; v1.y += r1.y;
            }
            *(float2*)(C + (long)row * N + col) = v0;
            *(float2*)(C + (long)(row + 8) * N + col) = v1;
        }
    }
    #undef LOAD_STAGE
}

// merged projection kernel: grid (N/128, 272). y<256 -> Q tiles; y>=256 -> KV.
__global__ __launch_bounds__(256, 2)
void proj_all(ProjBatch pb) {
    extern __shared__ bf16 sm[];
    const int t = threadIdx.x;
    const int lane = t & 31, wid = t >> 5;
    const int warp_m = wid >> 2, warp_n = wid & 3;
    const int bn = blockIdx.x * 128;
    const uint32_t sbase = smem_u32(sm);

    int e, bm;
    if (blockIdx.y < 256) { e = 0; bm = blockIdx.y * 128; }
    else { int y = blockIdx.y - 256; e = 1 + (y >> 2); bm = (y & 3) * 128; }

    gemm_core(pb.A[e], pb.W[e], pb.C[e], Dsz, pb.K[e], bm, bn,
              nullptr, nullptr, sm, sbase, t, lane, warp_m, warp_n);
}

// single GEMM (out projection with bias+residual)
__global__ __launch_bounds__(256, 2)
void gemm_out(const bf16* __restrict__ A, const bf16* __restrict__ W,
              float* __restrict__ C, int N, int K,
              const float* __restrict__ bias, const float* __restrict__ res) {
    extern __shared__ bf16 sm[];
    const int t = threadIdx.x;
    const int lane = t & 31, wid = t >> 5;
    gemm_core(A, W, C, N, K, blockIdx.y * 128, blockIdx.x * 128,
              bias, res, sm, smem_u32(sm), t, lane, wid >> 2, wid & 3);
}

// ---------------- fp32 -> bf16 conversion ------------------------------------
__global__ void f2bf(const float* __restrict__ x, bf16* __restrict__ y, int n4) {
    int i = blockIdx.x * blockDim.x + threadIdx.x;
    if (i >= n4) return;
    float4 v = ((const float4*)x)[i];
    uint2 o;
    o.x = pack_bf2(v.x, v.y);
    o.y = pack_bf2(v.z, v.w);
    ((uint2*)y)[i] = o;
}

struct ConvBatch { const float* src[6]; bf16* dst[6]; int n4[6]; };
__global__ void f2bf_batch(ConvBatch cb) {
    int seg = blockIdx.y;
    int i = blockIdx.x * blockDim.x + threadIdx.x;
    if (i >= cb.n4[seg]) return;
    float4 v = ((const float4*)cb.src[seg])[i];
    uint2 o;
    o.x = pack_bf2(v.x, v.y);
    o.y = pack_bf2(v.z, v.w);
    ((uint2*)cb.dst[seg])[i] = o;
}

// ---------------- gather encoder tokens (bf16) ------------------------------
__global__ void gather_tokens(const float* __restrict__ enc) {
    int i = blockIdx.x * blockDim.x + threadIdx.x;
    if (i >= Bsz*NTOK*CRS) return;
    int c = i % CRS;
    int tt = (i / CRS) % NTOK;
    int b = i / (CRS*NTOK);
    g_dis [i] = __float2bfloat16_rn(enc[((long)b*ETOK + tt)        * CRS + c]);
    g_anat[i] = __float2bfloat16_rn(enc[((long)b*ETOK + NTOK + tt) * CRS + c]);
}

// ---------------- per-batch gate scalars -----------------------------------
__global__ void gate_kernel(const float* __restrict__ w_gate,
                            const float* __restrict__ b_gate,
                            const float* __restrict__ anat_logit,
                            const float* __restrict__ dis_logit) {
    int b = blockIdx.x;
    __shared__ float red[256];
    float partial = 0.f;
    for (int c = threadIdx.x; c < CRS; c += 256) {
        float s = 0.f;
        #pragma unroll
        for (int t = 0; t < NTOK; t++)
            s += __bfloat162float(g_dis[(b*NTOK + t)*CRS + c]);
        partial += (s * (1.0f/NTOK)) * w_gate[c];
    }
    red[threadIdx.x] = partial;
    __syncthreads();
    for (int off = 128; off > 0; off >>= 1) {
        if (threadIdx.x < off) red[threadIdx.x] += red[threadIdx.x + off];
        __syncthreads();
    }
    if (threadIdx.x == 0) {
        float shift = red[0] + b_gate[0];
        g_gate[b*2+0] = 1.0f / (1.0f + expf(-(anat_logit[0] - shift)));
        g_gate[b*2+1] = 1.0f / (1.0f + expf(-(dis_logit[0]  + shift)));
    }
}

// ---------------- fused dual attention + gating (fp32 math, bf16 z out) -----
__global__ __launch_bounds__(128)
void attn_kernel() {
    __shared__ float ka[NTOK][HD], va[NTOK][HD], kd[NTOK][HD], vd[NTOK][HD];
    const int b = blockIdx.z, h = blockIdx.y;
    const int s = blockIdx.x * 128 + threadIdx.x;

    for (int i = threadIdx.x; i < NTOK*HD; i += 128) {
        int t = i / HD, d = i % HD;
        long src = (long)(b*NTOK + t) * Dsz + h*HD + d;
        ka[t][d] = g_ka[src];  va[t][d] = g_va[src];
        kd[t][d] = g_kd[src];  vd[t][d] = g_vd[src];
    }
    __syncthreads();

    const float ga = g_gate[b*2+0];
    const float gd = g_gate[b*2+1];

    float q[HD];
    const float* qp = g_q + ((long)(b*Ssz + s)) * Dsz + h*HD;
    #pragma unroll
    for (int d = 0; d < HD; d += 4) {
        float4 v = *(const float4*)(qp + d);
        q[d] = v.x; q[d+1] = v.y; q[d+2] = v.z; q[d+3] = v.w;
    }

    float out[HD];
    #pragma unroll
    for (int d = 0; d < HD; d++) out[d] = 0.f;
    float sc[NTOK];

    float mx = -1e30f;
    #pragma unroll
    for (int j = 0; j < NTOK; j++) {
        float s2 = 0.f;
        #pragma unroll
        for (int d = 0; d < HD; d++) s2 = fmaf(q[d], ka[j][d], s2);
        sc[j] = s2 * SCALE;  mx = fmaxf(mx, sc[j]);
    }
    float sum = 0.f;
    #pragma unroll
    for (int j = 0; j < NTOK; j++) { sc[j] = expf(sc[j] - mx); sum += sc[j]; }
    float inv = ga / sum;
    #pragma unroll
    for (int j = 0; j < NTOK; j++) {
        float p = sc[j] * inv;
        #pragma unroll
        for (int d = 0; d < HD; d++) out[d] = fmaf(p, va[j][d], out[d]);
    }

    mx = -1e30f;
    #pragma unroll
    for (int j = 0; j < NTOK; j++) {
        float s2 = 0.f;
        #pragma unroll
        for (int d = 0; d < HD; d++) s2 = fmaf(q[d], kd[j][d], s2);
        sc[j] = s2 * SCALE;  mx = fmaxf(mx, sc[j]);
    }
    sum = 0.f;
    #pragma unroll
    for (int j = 0; j < NTOK; j++) { sc[j] = expf(sc[j] - mx); sum += sc[j]; }
    inv = gd / sum;
    #pragma unroll
    for (int j = 0; j < NTOK; j++) {
        float p = sc[j] * inv;
        #pragma unroll
        for (int d = 0; d < HD; d++) out[d] = fmaf(p, vd[j][d], out[d]);
    }

    bf16* zp = g_z + ((long)(b*Ssz + s)) * Dsz + h*HD;
    #pragma unroll
    for (int d = 0; d < HD; d += 8) {
        uint4 o;
        o.x = pack_bf2(out[d],   out[d+1]);
        o.y = pack_bf2(out[d+2], out[d+3]);
        o.z = pack_bf2(out[d+4], out[d+5]);
        o.w = pack_bf2(out[d+6], out[d+7]);
        *(uint4*)(zp + d) = o;
    }
}

// ---------------- launch ----------------------------------------------------
extern "C" void kernel_launch(void* const* d_in, const int* in_sizes, int n_in,
                              void* d_out, int out_size) {
    const float* hidden  = (const float*)d_in[0];
    const float* enc     = (const float*)d_in[1];
    const float* w_q     = (const float*)d_in[2];
    const float* w_k     = (const float*)d_in[3];
    const float* w_v     = (const float*)d_in[4];
    const float* w_k_dis = (const float*)d_in[5];
    const float* w_v_dis = (const float*)d_in[6];
    const float* w_gate  = (const float*)d_in[7];
    const float* b_gate  = (const float*)d_in[8];
    const float* a_logit = (const float*)d_in[9];
    const float* d_logit = (const float*)d_in[10];
    const float* w_out   = (const float*)d_in[11];
    const float* b_out   = (const float*)d_in[12];
    float* out = (float*)d_out;

    bf16 *anat_p, *dis_p, *z_p, *hidb_p, *wq_p, *wout_p, *wka_p, *wva_p, *wkd_p, *wvd_p;
    float *ka_p, *va_p, *kd_p, *vd_p, *q_p;
    cudaGetSymbolAddress((void**)&anat_p, g_anat);
    cudaGetSymbolAddress((void**)&dis_p,  g_dis);
    cudaGetSymbolAddress((void**)&ka_p,   g_ka);
    cudaGetSymbolAddress((void**)&va_p,   g_va);
    cudaGetSymbolAddress((void**)&kd_p,   g_kd);
    cudaGetSymbolAddress((void**)&vd_p,   g_vd);
    cudaGetSymbolAddress((void**)&q_p,    g_q);
    cudaGetSymbolAddress((void**)&z_p,    g_z);
    cudaGetSymbolAddress((void**)&hidb_p, g_hidb);
    cudaGetSymbolAddress((void**)&wq_p,   g_wq);
    cudaGetSymbolAddress((void**)&wout_p, g_wout);
    cudaGetSymbolAddress((void**)&wka_p,  g_wka);
    cudaGetSymbolAddress((void**)&wva_p,  g_wva);
    cudaGetSymbolAddress((void**)&wkd_p,  g_wkd);
    cudaGetSymbolAddress((void**)&wvd_p,  g_wvd);

    cudaFuncSetAttribute(proj_all, cudaFuncAttributeMaxDynamicSharedMemorySize, GEMM_SMEM);
    cudaFuncSetAttribute(gemm_out, cudaFuncAttributeMaxDynamicSharedMemorySize, GEMM_SMEM);

    // conversions: hidden (big) + 6 weights (batched single launch)
    {
        int n4 = MS*Dsz/4;
        f2bf<<<(n4 + 255)/256, 256>>>(hidden, hidb_p, n4);
        ConvBatch cb;
        int w4 = Dsz*Dsz/4, k4 = Dsz*CRS/4;
        cb.src[0] = w_q;     cb.dst[0] = wq_p;   cb.n4[0] = w4;
        cb.src[1] = w_out;   cb.dst[1] = wout_p; cb.n4[1] = w4;
        cb.src[2] = w_k;     cb.dst[2] = wka_p;  cb.n4[2] = k4;
        cb.src[3] = w_v;     cb.dst[3] = wva_p;  cb.n4[3] = k4;
        cb.src[4] = w_k_dis; cb.dst[4] = wkd_p;  cb.n4[4] = k4;
        cb.src[5] = w_v_dis; cb.dst[5] = wvd_p;  cb.n4[5] = k4;
        dim3 grid((w4 + 255)/256, 6);
        f2bf_batch<<<grid, 256>>>(cb);
    }
    { int n = Bsz*NTOK*CRS; gather_tokens<<<(n + 255)/256, 256>>>(enc); }
    gate_kernel<<<Bsz, 256>>>(w_gate, b_gate, a_logit, d_logit);

    // merged Q + KV projections (one launch, 2720 CTAs)
    {
        ProjBatch pb;
        pb.A[0] = hidb_p; pb.W[0] = wq_p;  pb.C[0] = q_p;  pb.K[0] = Dsz;
        pb.A[1] = anat_p; pb.W[1] = wka_p; pb.C[1] = ka_p; pb.K[1] = CRS;
        pb.A[2] = anat_p; pb.W[2] = wva_p; pb.C[2] = va_p; pb.K[2] = CRS;
        pb.A[3] = dis_p;  pb.W[3] = wkd_p; pb.C[3] = kd_p; pb.K[3] = CRS;
        pb.A[4] = dis_p;  pb.W[4] = wvd_p; pb.C[4] = vd_p; pb.K[4] = CRS;
        dim3 grid(Dsz/128, 256 + 16);
        proj_all<<<grid, 256, GEMM_SMEM>>>(pb);
    }
    // attention + gating
    {
        dim3 grid(Ssz/128, HEADS, Bsz);
        attn_kernel<<<grid, 128>>>();
    }
    // out projection + bias + residual
    {
        dim3 grid(Dsz/128, MS/128);
        gemm_out<<<grid, 256, GEMM_SMEM>>>(z_p, wout_p, out, Dsz, Dsz, b_out, hidden);
    }
}

// round 8
// speedup vs baseline: 7.8374x; 1.2851x over previous
#include <cuda_runtime.h>
#include <cuda_bf16.h>
#include <math.h>
#include <stdint.h>

#define Bsz   32
#define Ssz   1024
#define Dsz   1280
#define CRS   768
#define HEADS 20
#define HD    64
#define NTOK  16
#define ETOK  48
#define MS    (Bsz*Ssz)
#define SCALE 0.125f

typedef __nv_bfloat16 bf16;

// ---------------- scratch (device globals: allocation-free) ----------------
__device__ bf16  g_qb [MS*Dsz];            // bf16 Q
__device__ bf16  g_z  [MS*Dsz];            // bf16 attention output
__device__ bf16  g_hidb[MS*Dsz];           // bf16 hidden
__device__ bf16  g_anat[Bsz*NTOK*CRS];
__device__ bf16  g_dis [Bsz*NTOK*CRS];
__device__ float g_ka [Bsz*NTOK*Dsz];
__device__ float g_va [Bsz*NTOK*Dsz];
__device__ float g_kd [Bsz*NTOK*Dsz];
__device__ float g_vd [Bsz*NTOK*Dsz];
__device__ float g_gate[Bsz*2];
__device__ bf16  g_wq  [Dsz*Dsz];
__device__ bf16  g_wout[Dsz*Dsz];
__device__ bf16  g_wka [Dsz*CRS];
__device__ bf16  g_wva [Dsz*CRS];
__device__ bf16  g_wkd [Dsz*CRS];
__device__ bf16  g_wvd [Dsz*CRS];

// ---------------- helpers ---------------------------------------------------
__device__ __forceinline__ uint32_t smem_u32(const void* p) {
    uint32_t a;
    asm("{ .reg .u64 t; cvta.to.shared.u64 t, %1; cvt.u32.u64 %0, t; }" : "=r"(a) : "l"(p));
    return a;
}
__device__ __forceinline__ void cp16(uint32_t dst, const void* src) {
    asm volatile("cp.async.cg.shared.global [%0], [%1], 16;" :: "r"(dst), "l"(src));
}
#define CP_COMMIT() asm volatile("cp.async.commit_group;" ::: "memory")
#define CP_WAIT0()  asm volatile("cp.async.wait_group 0;" ::: "memory")

__device__ __forceinline__ uint32_t pack_bf2(float lo, float hi) {
    __nv_bfloat162 v = __floats2bfloat162_rn(lo, hi);
    return *(uint32_t*)&v;
}
__device__ __forceinline__ void ldsm4(uint32_t* r, uint32_t addr) {
    asm volatile("ldmatrix.sync.aligned.m8n8.x4.shared.b16 {%0,%1,%2,%3}, [%4];"
                 : "=r"(r[0]), "=r"(r[1]), "=r"(r[2]), "=r"(r[3]) : "r"(addr));
}
__device__ __forceinline__ void mma16(float* d, const uint32_t* a, const uint32_t* b) {
    asm volatile(
        "mma.sync.aligned.m16n8k16.row.col.f32.bf16.bf16.f32 "
        "{%0,%1,%2,%3}, {%4,%5,%6,%7}, {%8,%9}, {%0,%1,%2,%3};"
        : "+f"(d[0]), "+f"(d[1]), "+f"(d[2]), "+f"(d[3])
        : "r"(a[0]), "r"(a[1]), "r"(a[2]), "r"(a[3]), "r"(b[0]), "r"(b[1]));
}

// ---------------- bf16 mma.sync GEMM (single-sync pipeline) -----------------
#define LDE 72
#define TILE_E (128*LDE)
#define TILE_BYTES (TILE_E*2)          // 18432
#define STAGE_BYTES (2*TILE_BYTES)     // 36864
#define GEMM_SMEM (2*STAGE_BYTES)      // 73728

struct ProjBatch {
    const bf16* A[5];
    const bf16* W[5];
    void*       C[5];
    int         K[5];
};

__device__ __forceinline__ void gemm_core(
    const bf16* __restrict__ A, const bf16* __restrict__ W,
    void* __restrict__ C, int N, int K, int bm, int bn, bool obf,
    const float* __restrict__ bias, const float* __restrict__ res,
    bf16* sm, uint32_t sbase, int t, int lane, int warp_m, int warp_n)
{
    const int NIT = K / 64;

    const uint32_t aLane = ((uint32_t)(warp_m*64 + (lane & 15)) * LDE
                          + ((lane >> 4) << 3)) * 2;
    const uint32_t bLane = ((uint32_t)(warp_n*32 + ((lane >> 4) << 3) + (lane & 7)) * LDE
                          + (((lane >> 3) & 1) << 3)) * 2;

    float acc[4][4][4];
    #pragma unroll
    for (int i = 0; i < 4; i++)
        #pragma unroll
        for (int j = 0; j < 4; j++)
            #pragma unroll
            for (int r = 0; r < 4; r++) acc[i][j][r] = 0.f;

    #define LOAD_STAGE(IT, S) do {                                             \
        const bf16* Ab = A + (long)bm * K + (IT) * 64;                         \
        const bf16* Wb = W + (long)bn * K + (IT) * 64;                         \
        uint32_t dA = sbase + (S) * STAGE_BYTES;                               \
        uint32_t dB = dA + TILE_BYTES;                                         \
        _Pragma("unroll")                                                      \
        for (int i = 0; i < 4; i++) {                                          \
            int idx = i * 256 + t; int row = idx >> 3, g = idx & 7;            \
            cp16(dA + row * (LDE*2) + g * 16, Ab + (long)row * K + g * 8);     \
        }                                                                      \
        _Pragma("unroll")                                                      \
        for (int i = 0; i < 4; i++) {                                          \
            int idx = i * 256 + t; int row = idx >> 3, g = idx & 7;            \
            cp16(dB + row * (LDE*2) + g * 16, Wb + (long)row * K + g * 8);     \
        }                                                                      \
        CP_COMMIT();                                                           \
    } while (0)

    LOAD_STAGE(0, 0);

    for (int it = 0; it < NIT; it++) {
        int s = it & 1;
        CP_WAIT0();
        __syncthreads();
        if (it + 1 < NIT)
            LOAD_STAGE(it + 1, s ^ 1);

        const uint32_t aBase = sbase + s * STAGE_BYTES + aLane;
        const uint32_t bBase = sbase + s * STAGE_BYTES + TILE_BYTES + bLane;
        #pragma unroll
        for (int ks = 0; ks < 4; ks++) {
            uint32_t a[4][4], bb[2][4];
            #pragma unroll
            for (int mt = 0; mt < 4; mt++)
                ldsm4(a[mt], aBase + mt * (16*LDE*2) + ks * 32);
            #pragma unroll
            for (int j = 0; j < 2; j++)
                ldsm4(bb[j], bBase + j * (16*LDE*2) + ks * 32);
            #pragma unroll
            for (int mt = 0; mt < 4; mt++)
                #pragma unroll
                for (int nt = 0; nt < 4; nt++)
                    mma16(acc[mt][nt], a[mt], &bb[nt >> 1][(nt & 1) * 2]);
        }
    }

    #pragma unroll
    for (int mt = 0; mt < 4; mt++) {
        #pragma unroll
        for (int nt = 0; nt < 4; nt++) {
            int row = bm + warp_m * 64 + mt * 16 + (lane >> 2);
            int col = bn + warp_n * 32 + nt * 8 + 2 * (lane & 3);
            float2 v0 = make_float2(acc[mt][nt][0], acc[mt][nt][1]);
            float2 v1 = make_float2(acc[mt][nt][2], acc[mt][nt][3]);
            if (obf) {
                bf16* Cb = (bf16*)C;
                *(uint32_t*)(Cb + (long)row * N + col)       = pack_bf2(v0.x, v0.y);
                *(uint32_t*)(Cb + (long)(row + 8) * N + col) = pack_bf2(v1.x, v1.y);
            } else {
                float* Cf = (float*)C;
                if (bias) {
                    float2 bb = *(const float2*)(bias + col);
                    v0.x += bb.x; v0.y += bb.y; v1.x += bb.x; v1.y += bb.y;
                }
                if (res) {
                    float2 r0 = *(const float2*)(res + (long)row * N + col);
                    float2 r1 = *(const float2*)(res + (long)(row + 8) * N + col);
                    v0.x += r0.x; v0.y += r0.y; v1.x += r1.x; v1.y += r1.y;
                }
                *(float2*)(Cf + (long)row * N + col) = v0;
                *(float2*)(Cf + (long)(row + 8) * N + col) = v1;
            }
        }
    }
    #undef LOAD_STAGE
}

// merged projection kernel: grid (N/128, 272). y<256 -> Q tiles; y>=256 -> KV.
__global__ __launch_bounds__(256, 2)
void proj_all(ProjBatch pb) {
    extern __shared__ bf16 sm[];
    const int t = threadIdx.x;
    const int lane = t & 31, wid = t >> 5;
    const int bn = blockIdx.x * 128;
    const uint32_t sbase = smem_u32(sm);

    int e, bm;
    if (blockIdx.y < 256) { e = 0; bm = blockIdx.y * 128; }
    else { int y = blockIdx.y - 256; e = 1 + (y >> 2); bm = (y & 3) * 128; }

    gemm_core(pb.A[e], pb.W[e], pb.C[e], Dsz, pb.K[e], bm, bn, (e == 0),
              nullptr, nullptr, sm, sbase, t, lane, wid >> 2, wid & 3);
}

__global__ __launch_bounds__(256, 2)
void gemm_out(const bf16* __restrict__ A, const bf16* __restrict__ W,
              float* __restrict__ C, int N, int K,
              const float* __restrict__ bias, const float* __restrict__ res) {
    extern __shared__ bf16 sm[];
    const int t = threadIdx.x;
    const int lane = t & 31, wid = t >> 5;
    gemm_core(A, W, C, N, K, blockIdx.y * 128, blockIdx.x * 128, false,
              bias, res, sm, smem_u32(sm), t, lane, wid >> 2, wid & 3);
}

// ---------------- fp32 -> bf16 conversion ------------------------------------
__global__ void f2bf(const float* __restrict__ x, bf16* __restrict__ y, int n4) {
    int i = blockIdx.x * blockDim.x + threadIdx.x;
    if (i >= n4) return;
    float4 v = ((const float4*)x)[i];
    uint2 o;
    o.x = pack_bf2(v.x, v.y);
    o.y = pack_bf2(v.z, v.w);
    ((uint2*)y)[i] = o;
}

struct ConvBatch { const float* src[6]; bf16* dst[6]; int n4[6]; };
__global__ void f2bf_batch(ConvBatch cb) {
    int seg = blockIdx.y;
    int i = blockIdx.x * blockDim.x + threadIdx.x;
    if (i >= cb.n4[seg]) return;
    float4 v = ((const float4*)cb.src[seg])[i];
    uint2 o;
    o.x = pack_bf2(v.x, v.y);
    o.y = pack_bf2(v.z, v.w);
    ((uint2*)cb.dst[seg])[i] = o;
}

// ---------------- gather encoder tokens (bf16) ------------------------------
__global__ void gather_tokens(const float* __restrict__ enc) {
    int i = blockIdx.x * blockDim.x + threadIdx.x;
    if (i >= Bsz*NTOK*CRS) return;
    int c = i % CRS;
    int tt = (i / CRS) % NTOK;
    int b = i / (CRS*NTOK);
    g_dis [i] = __float2bfloat16_rn(enc[((long)b*ETOK + tt)        * CRS + c]);
    g_anat[i] = __float2bfloat16_rn(enc[((long)b*ETOK + NTOK + tt) * CRS + c]);
}

// ---------------- per-batch gate scalars -----------------------------------
__global__ void gate_kernel(const float* __restrict__ w_gate,
                            const float* __restrict__ b_gate,
                            const float* __restrict__ anat_logit,
                            const float* __restrict__ dis_logit) {
    int b = blockIdx.x;
    __shared__ float red[256];
    float partial = 0.f;
    for (int c = threadIdx.x; c < CRS; c += 256) {
        float s = 0.f;
        #pragma unroll
        for (int t = 0; t < NTOK; t++)
            s += __bfloat162float(g_dis[(b*NTOK + t)*CRS + c]);
        partial += (s * (1.0f/NTOK)) * w_gate[c];
    }
    red[threadIdx.x] = partial;
    __syncthreads();
    for (int off = 128; off > 0; off >>= 1) {
        if (threadIdx.x < off) red[threadIdx.x] += red[threadIdx.x + off];
        __syncthreads();
    }
    if (threadIdx.x == 0) {
        float shift = red[0] + b_gate[0];
        g_gate[b*2+0] = 1.0f / (1.0f + expf(-(anat_logit[0] - shift)));
        g_gate[b*2+1] = 1.0f / (1.0f + expf(-(dis_logit[0]  + shift)));
    }
}

// ---------------- mma attention: one CTA = 128 queries x 1 head -------------
#define VP 24

__device__ __forceinline__ void attend_branch(
    const bf16* sK, const bf16* sV, float gate, int lane,
    const uint32_t (&qf)[2][4][4], float (&out)[2][8][4])
{
    // K fragments: B operand for scores (n=token, k=dim)
    uint32_t bk[2][4][2];
    #pragma unroll
    for (int n = 0; n < 2; n++)
        #pragma unroll
        for (int k = 0; k < 4; k++) {
            const bf16* p = &sK[(n*8 + (lane >> 2))*72 + k*16 + 2*(lane & 3)];
            bk[n][k][0] = *(const uint32_t*)p;
            bk[n][k][1] = *(const uint32_t*)(p + 8);
        }
    // V fragments: B operand for P@V (n=dim, k=token)
    uint32_t bv[8][2];
    #pragma unroll
    for (int n8 = 0; n8 < 8; n8++) {
        const bf16* p = &sV[(n8*8 + (lane >> 2))*VP + 2*(lane & 3)];
        bv[n8][0] = *(const uint32_t*)p;
        bv[n8][1] = *(const uint32_t*)(p + 8);
    }

    float sc[2][2][4];
    #pragma unroll
    for (int m = 0; m < 2; m++)
        #pragma unroll
        for (int n = 0; n < 2; n++) {
            #pragma unroll
            for (int r = 0; r < 4; r++) sc[m][n][r] = 0.f;
            #pragma unroll
            for (int k = 0; k < 4; k++)
                mma16(sc[m][n], qf[m][k], bk[n][k]);
        }

    #pragma unroll
    for (int m = 0; m < 2; m++) {
        float v[2][4];
        #pragma unroll
        for (int n = 0; n < 2; n++)
            #pragma unroll
            for (int r = 0; r < 4; r++) v[n][r] = sc[m][n][r] * SCALE;

        float mx0 = fmaxf(fmaxf(v[0][0], v[0][1]), fmaxf(v[1][0], v[1][1]));
        float mx1 = fmaxf(fmaxf(v[0][2], v[0][3]), fmaxf(v[1][2], v[1][3]));
        mx0 = fmaxf(mx0, __shfl_xor_sync(0xffffffffu, mx0, 1));
        mx0 = fmaxf(mx0, __shfl_xor_sync(0xffffffffu, mx0, 2));
        mx1 = fmaxf(mx1, __shfl_xor_sync(0xffffffffu, mx1, 1));
        mx1 = fmaxf(mx1, __shfl_xor_sync(0xffffffffu, mx1, 2));

        float e[2][4];
        #pragma unroll
        for (int n = 0; n < 2; n++) {
            e[n][0] = expf(v[n][0] - mx0);
            e[n][1] = expf(v[n][1] - mx0);
            e[n][2] = expf(v[n][2] - mx1);
            e[n][3] = expf(v[n][3] - mx1);
        }
        float s0 = e[0][0] + e[0][1] + e[1][0] + e[1][1];
        float s1 = e[0][2] + e[0][3] + e[1][2] + e[1][3];
        s0 += __shfl_xor_sync(0xffffffffu, s0, 1);
        s0 += __shfl_xor_sync(0xffffffffu, s0, 2);
        s1 += __shfl_xor_sync(0xffffffffu, s1, 1);
        s1 += __shfl_xor_sync(0xffffffffu, s1, 2);
        float i0 = gate / s0, i1 = gate / s1;

        uint32_t pf[4];
        pf[0] = pack_bf2(e[0][0]*i0, e[0][1]*i0);   // row r,   tokens 0-7 slice
        pf[1] = pack_bf2(e[0][2]*i1, e[0][3]*i1);   // row r+8, tokens 0-7 slice
        pf[2] = pack_bf2(e[1][0]*i0, e[1][1]*i0);   // row r,   tokens 8-15 slice
        pf[3] = pack_bf2(e[1][2]*i1, e[1][3]*i1);   // row r+8, tokens 8-15 slice

        #pragma unroll
        for (int n8 = 0; n8 < 8; n8++)
            mma16(out[m][n8], pf, bv[n8]);
    }
}

__global__ __launch_bounds__(128)
void attn_mma() {
    __shared__ bf16 sQ[128*72];
    __shared__ bf16 sKa[16*72], sKd[16*72];
    __shared__ bf16 sVa[64*VP], sVd[64*VP];
    const int b = blockIdx.z, h = blockIdx.y, bx = blockIdx.x;
    const int t = threadIdx.x, lane = t & 31, w = t >> 5;

    const long qbase = ((long)(b*Ssz) + bx*128) * Dsz + h*HD;
    #pragma unroll
    for (int i = 0; i < 8; i++) {
        int idx = i*128 + t;
        int row = idx >> 3, c8 = idx & 7;
        uint4 v = *(const uint4*)(g_qb + qbase + (long)row*Dsz + c8*8);
        *(uint4*)&sQ[row*72 + c8*8] = v;
    }
    {
        const float* ka = g_ka + ((long)b*NTOK)*Dsz + h*HD;
        const float* kd = g_kd + ((long)b*NTOK)*Dsz + h*HD;
        #pragma unroll
        for (int i = 0; i < 4; i++) {
            int idx = i*128 + t;
            int d2 = idx & 31, tok = idx >> 5;
            float2 va = *(const float2*)(ka + (long)tok*Dsz + 2*d2);
            float2 vd = *(const float2*)(kd + (long)tok*Dsz + 2*d2);
            *(uint32_t*)&sKa[tok*72 + 2*d2] = pack_bf2(va.x, va.y);
            *(uint32_t*)&sKd[tok*72 + 2*d2] = pack_bf2(vd.x, vd.y);
        }
    }
    {
        const float* va = g_va + ((long)b*NTOK)*Dsz + h*HD;
        const float* vd = g_vd + ((long)b*NTOK)*Dsz + h*HD;
        #pragma unroll
        for (int i = 0; i < 8; i++) {
            int idx = i*128 + t;
            int d = idx & 63, tok = idx >> 6;
            sVa[d*VP + tok] = __float2bfloat16_rn(va[(long)tok*Dsz + d]);
            sVd[d*VP + tok] = __float2bfloat16_rn(vd[(long)tok*Dsz + d]);
        }
    }
    __syncthreads();

    const float ga = g_gate[b*2+0], gd = g_gate[b*2+1];

    uint32_t qf[2][4][4];
    #pragma unroll
    for (int m = 0; m < 2; m++)
        #pragma unroll
        for (int k = 0; k < 4; k++) {
            uint32_t addr = smem_u32(
                &sQ[(w*32 + m*16 + (lane & 15))*72 + k*16 + ((lane >> 4) << 3)]);
            ldsm4(qf[m][k], addr);
        }

    float out[2][8][4];
    #pragma unroll
    for (int m = 0; m < 2; m++)
        #pragma unroll
        for (int n = 0; n < 8; n++)
            #pragma unroll
            for (int r = 0; r < 4; r++) out[m][n][r] = 0.f;

    attend_branch(sKa, sVa, ga, lane, qf, out);
    attend_branch(sKd, sVd, gd, lane, qf, out);

    const long zbase = ((long)(b*Ssz) + bx*128 + w*32) * Dsz + h*HD;
    const int r = lane >> 2, c = 2 * (lane & 3);
    #pragma unroll
    for (int m = 0; m < 2; m++)
        #pragma unroll
        for (int n8 = 0; n8 < 8; n8++) {
            long ro = zbase + (long)(m*16 + r) * Dsz + n8*8 + c;
            *(uint32_t*)(g_z + ro)          = pack_bf2(out[m][n8][0], out[m][n8][1]);
            *(uint32_t*)(g_z + ro + 8*Dsz)  = pack_bf2(out[m][n8][2], out[m][n8][3]);
        }
}

// ---------------- launch ----------------------------------------------------
extern "C" void kernel_launch(void* const* d_in, const int* in_sizes, int n_in,
                              void* d_out, int out_size) {
    const float* hidden  = (const float*)d_in[0];
    const float* enc     = (const float*)d_in[1];
    const float* w_q     = (const float*)d_in[2];
    const float* w_k     = (const float*)d_in[3];
    const float* w_v     = (const float*)d_in[4];
    const float* w_k_dis = (const float*)d_in[5];
    const float* w_v_dis = (const float*)d_in[6];
    const float* w_gate  = (const float*)d_in[7];
    const float* b_gate  = (const float*)d_in[8];
    const float* a_logit = (const float*)d_in[9];
    const float* d_logit = (const float*)d_in[10];
    const float* w_out   = (const float*)d_in[11];
    const float* b_out   = (const float*)d_in[12];
    float* out = (float*)d_out;

    bf16 *anat_p, *dis_p, *z_p, *hidb_p, *qb_p, *wq_p, *wout_p, *wka_p, *wva_p, *wkd_p, *wvd_p;
    float *ka_p, *va_p, *kd_p, *vd_p;
    cudaGetSymbolAddress((void**)&anat_p, g_anat);
    cudaGetSymbolAddress((void**)&dis_p,  g_dis);
    cudaGetSymbolAddress((void**)&ka_p,   g_ka);
    cudaGetSymbolAddress((void**)&va_p,   g_va);
    cudaGetSymbolAddress((void**)&kd_p,   g_kd);
    cudaGetSymbolAddress((void**)&vd_p,   g_vd);
    cudaGetSymbolAddress((void**)&qb_p,   g_qb);
    cudaGetSymbolAddress((void**)&z_p,    g_z);
    cudaGetSymbolAddress((void**)&hidb_p, g_hidb);
    cudaGetSymbolAddress((void**)&wq_p,   g_wq);
    cudaGetSymbolAddress((void**)&wout_p, g_wout);
    cudaGetSymbolAddress((void**)&wka_p,  g_wka);
    cudaGetSymbolAddress((void**)&wva_p,  g_wva);
    cudaGetSymbolAddress((void**)&wkd_p,  g_wkd);
    cudaGetSymbolAddress((void**)&wvd_p,  g_wvd);

    cudaFuncSetAttribute(proj_all, cudaFuncAttributeMaxDynamicSharedMemorySize, GEMM_SMEM);
    cudaFuncSetAttribute(gemm_out, cudaFuncAttributeMaxDynamicSharedMemorySize, GEMM_SMEM);

    // conversions: hidden (big) + 6 weights (batched single launch)
    {
        int n4 = MS*Dsz/4;
        f2bf<<<(n4 + 255)/256, 256>>>(hidden, hidb_p, n4);
        ConvBatch cb;
        int w4 = Dsz*Dsz/4, k4 = Dsz*CRS/4;
        cb.src[0] = w_q;     cb.dst[0] = wq_p;   cb.n4[0] = w4;
        cb.src[1] = w_out;   cb.dst[1] = wout_p; cb.n4[1] = w4;
        cb.src[2] = w_k;     cb.dst[2] = wka_p;  cb.n4[2] = k4;
        cb.src[3] = w_v;     cb.dst[3] = wva_p;  cb.n4[3] = k4;
        cb.src[4] = w_k_dis; cb.dst[4] = wkd_p;  cb.n4[4] = k4;
        cb.src[5] = w_v_dis; cb.dst[5] = wvd_p;  cb.n4[5] = k4;
        dim3 grid((w4 + 255)/256, 6);
        f2bf_batch<<<grid, 256>>>(cb);
    }
    { int n = Bsz*NTOK*CRS; gather_tokens<<<(n + 255)/256, 256>>>(enc); }
    gate_kernel<<<Bsz, 256>>>(w_gate, b_gate, a_logit, d_logit);

    // merged Q + KV projections (one launch, 2720 CTAs)
    {
        ProjBatch pb;
        pb.A[0] = hidb_p; pb.W[0] = wq_p;  pb.C[0] = qb_p; pb.K[0] = Dsz;
        pb.A[1] = anat_p; pb.W[1] = wka_p; pb.C[1] = ka_p; pb.K[1] = CRS;
        pb.A[2] = anat_p; pb.W[2] = wva_p; pb.C[2] = va_p; pb.K[2] = CRS;
        pb.A[3] = dis_p;  pb.W[3] = wkd_p; pb.C[3] = kd_p; pb.K[3] = CRS;
        pb.A[4] = dis_p;  pb.W[4] = wvd_p; pb.C[4] = vd_p; pb.K[4] = CRS;
        dim3 grid(Dsz/128, 256 + 16);
        proj_all<<<grid, 256, GEMM_SMEM>>>(pb);
    }
    // mma attention + gating
    {
        dim3 grid(Ssz/128, HEADS, Bsz);
        attn_mma<<<grid, 128>>>();
    }
    // out projection + bias + residual
    {
        dim3 grid(Dsz/128, MS/128);
        gemm_out<<<grid, 256, GEMM_SMEM>>>(z_p, wout_p, out, Dsz, Dsz, b_out, hidden);
    }
}

// round 9
// speedup vs baseline: 7.8642x; 1.0034x over previous
#include <cuda_runtime.h>
#include <cuda_bf16.h>
#include <math.h>
#include <stdint.h>

#define Bsz   32
#define Ssz   1024
#define Dsz   1280
#define CRS   768
#define HEADS 20
#define HD    64
#define NTOK  16
#define ETOK  48
#define MS    (Bsz*Ssz)
#define SCALE 0.125f

typedef __nv_bfloat16 bf16;

// ---------------- scratch (device globals: allocation-free) ----------------
__device__ bf16  g_qb [MS*Dsz];            // bf16 Q
__device__ bf16  g_z  [MS*Dsz];            // bf16 attention output
__device__ bf16  g_hidb[MS*Dsz];           // bf16 hidden
__device__ bf16  g_anat[Bsz*NTOK*CRS];
__device__ bf16  g_dis [Bsz*NTOK*CRS];
__device__ float g_ka [Bsz*NTOK*Dsz];
__device__ float g_va [Bsz*NTOK*Dsz];
__device__ float g_kd [Bsz*NTOK*Dsz];
__device__ float g_vd [Bsz*NTOK*Dsz];
__device__ float g_gate[Bsz*2];
__device__ bf16  g_wq  [Dsz*Dsz];
__device__ bf16  g_wout[Dsz*Dsz];
__device__ bf16  g_wka [Dsz*CRS];
__device__ bf16  g_wva [Dsz*CRS];
__device__ bf16  g_wkd [Dsz*CRS];
__device__ bf16  g_wvd [Dsz*CRS];

// ---------------- helpers ---------------------------------------------------
__device__ __forceinline__ uint32_t smem_u32(const void* p) {
    uint32_t a;
    asm("{ .reg .u64 t; cvta.to.shared.u64 t, %1; cvt.u32.u64 %0, t; }" : "=r"(a) : "l"(p));
    return a;
}
__device__ __forceinline__ void cp16(uint32_t dst, const void* src) {
    asm volatile("cp.async.cg.shared.global [%0], [%1], 16;" :: "r"(dst), "l"(src));
}
#define CP_COMMIT() asm volatile("cp.async.commit_group;" ::: "memory")
#define CP_WAIT0()  asm volatile("cp.async.wait_group 0;" ::: "memory")

__device__ __forceinline__ uint32_t pack_bf2(float lo, float hi) {
    __nv_bfloat162 v = __floats2bfloat162_rn(lo, hi);
    return *(uint32_t*)&v;
}
__device__ __forceinline__ void ldsm4(uint32_t* r, uint32_t addr) {
    asm volatile("ldmatrix.sync.aligned.m8n8.x4.shared.b16 {%0,%1,%2,%3}, [%4];"
                 : "=r"(r[0]), "=r"(r[1]), "=r"(r[2]), "=r"(r[3]) : "r"(addr));
}
__device__ __forceinline__ void mma16(float* d, const uint32_t* a, const uint32_t* b) {
    asm volatile(
        "mma.sync.aligned.m16n8k16.row.col.f32.bf16.bf16.f32 "
        "{%0,%1,%2,%3}, {%4,%5,%6,%7}, {%8,%9}, {%0,%1,%2,%3};"
        : "+f"(d[0]), "+f"(d[1]), "+f"(d[2]), "+f"(d[3])
        : "r"(a[0]), "r"(a[1]), "r"(a[2]), "r"(a[3]), "r"(b[0]), "r"(b[1]));
}

// ---------------- bf16 mma.sync GEMM (4 warps, 64x64 warp tile) -------------
// BM=BN=128, BK=64. 4 warps (2x2), warp tile 64x64. Double-buffered cp.async.
#define LDE 72
#define TILE_E (128*LDE)
#define TILE_BYTES (TILE_E*2)          // 18432
#define STAGE_BYTES (2*TILE_BYTES)     // 36864
#define GEMM_SMEM (2*STAGE_BYTES)      // 73728

struct ProjBatch {
    const bf16* A[5];
    const bf16* W[5];
    void*       C[5];
    int         K[5];
};

__device__ __forceinline__ void gemm_core(
    const bf16* __restrict__ A, const bf16* __restrict__ W,
    void* __restrict__ C, int N, int K, int bm, int bn, bool obf,
    const float* __restrict__ bias, const float* __restrict__ res,
    bf16* sm, uint32_t sbase, int t, int lane, int warp_m, int warp_n)
{
    const int NIT = K / 64;

    const uint32_t aLane = ((uint32_t)(warp_m*64 + (lane & 15)) * LDE
                          + ((lane >> 4) << 3)) * 2;
    const uint32_t bLane = ((uint32_t)(warp_n*64 + ((lane >> 4) << 3) + (lane & 7)) * LDE
                          + (((lane >> 3) & 1) << 3)) * 2;

    float acc[4][8][4];
    #pragma unroll
    for (int i = 0; i < 4; i++)
        #pragma unroll
        for (int j = 0; j < 8; j++)
            #pragma unroll
            for (int r = 0; r < 4; r++) acc[i][j][r] = 0.f;

    #define LOAD_STAGE(IT, S) do {                                             \
        const bf16* Ab = A + (long)bm * K + (IT) * 64;                         \
        const bf16* Wb = W + (long)bn * K + (IT) * 64;                         \
        uint32_t dA = sbase + (S) * STAGE_BYTES;                               \
        uint32_t dB = dA + TILE_BYTES;                                         \
        _Pragma("unroll")                                                      \
        for (int i = 0; i < 8; i++) {                                          \
            int idx = i * 128 + t; int row = idx >> 3, g = idx & 7;            \
            cp16(dA + row * (LDE*2) + g * 16, Ab + (long)row * K + g * 8);     \
        }                                                                      \
        _Pragma("unroll")                                                      \
        for (int i = 0; i < 8; i++) {                                          \
            int idx = i * 128 + t; int row = idx >> 3, g = idx & 7;            \
            cp16(dB + row * (LDE*2) + g * 16, Wb + (long)row * K + g * 8);     \
        }                                                                      \
        CP_COMMIT();                                                           \
    } while (0)

    LOAD_STAGE(0, 0);

    for (int it = 0; it < NIT; it++) {
        int s = it & 1;
        CP_WAIT0();
        __syncthreads();
        if (it + 1 < NIT)
            LOAD_STAGE(it + 1, s ^ 1);

        const uint32_t aBase = sbase + s * STAGE_BYTES + aLane;
        const uint32_t bBase = sbase + s * STAGE_BYTES + TILE_BYTES + bLane;
        #pragma unroll
        for (int ks = 0; ks < 4; ks++) {
            uint32_t a[4][4], bb[4][4];
            #pragma unroll
            for (int mt = 0; mt < 4; mt++)
                ldsm4(a[mt], aBase + mt * (16*LDE*2) + ks * 32);
            #pragma unroll
            for (int j = 0; j < 4; j++)
                ldsm4(bb[j], bBase + j * (16*LDE*2) + ks * 32);
            #pragma unroll
            for (int mt = 0; mt < 4; mt++)
                #pragma unroll
                for (int nt = 0; nt < 8; nt++)
                    mma16(acc[mt][nt], a[mt], &bb[nt >> 1][(nt & 1) * 2]);
        }
    }

    #pragma unroll
    for (int mt = 0; mt < 4; mt++) {
        #pragma unroll
        for (int nt = 0; nt < 8; nt++) {
            int row = bm + warp_m * 64 + mt * 16 + (lane >> 2);
            int col = bn + warp_n * 64 + nt * 8 + 2 * (lane & 3);
            float2 v0 = make_float2(acc[mt][nt][0], acc[mt][nt][1]);
            float2 v1 = make_float2(acc[mt][nt][2], acc[mt][nt][3]);
            if (obf) {
                bf16* Cb = (bf16*)C;
                *(uint32_t*)(Cb + (long)row * N + col)       = pack_bf2(v0.x, v0.y);
                *(uint32_t*)(Cb + (long)(row + 8) * N + col) = pack_bf2(v1.x, v1.y);
            } else {
                float* Cf = (float*)C;
                if (bias) {
                    float2 bb = *(const float2*)(bias + col);
                    v0.x += bb.x; v0.y += bb.y; v1.x += bb.x; v1.y += bb.y;
                }
                if (res) {
                    float2 r0 = *(const float2*)(res + (long)row * N + col);
                    float2 r1 = *(const float2*)(res + (long)(row + 8) * N + col);
                    v0.x += r0.x; v0.y += r0.y; v1.x += r1.x; v1.y += r1.y;
                }
                *(float2*)(Cf + (long)row * N + col) = v0;
                *(float2*)(Cf + (long)(row + 8) * N + col) = v1;
            }
        }
    }
    #undef LOAD_STAGE
}

// merged projection kernel: grid (N/128, 272). y<256 -> Q tiles; y>=256 -> KV.
__global__ __launch_bounds__(128, 2)
void proj_all(ProjBatch pb) {
    extern __shared__ bf16 sm[];
    const int t = threadIdx.x;
    const int lane = t & 31, wid = t >> 5;
    const int bn = blockIdx.x * 128;
    const uint32_t sbase = smem_u32(sm);

    int e, bm;
    if (blockIdx.y < 256) { e = 0; bm = blockIdx.y * 128; }
    else { int y = blockIdx.y - 256; e = 1 + (y >> 2); bm = (y & 3) * 128; }

    gemm_core(pb.A[e], pb.W[e], pb.C[e], Dsz, pb.K[e], bm, bn, (e == 0),
              nullptr, nullptr, sm, sbase, t, lane, wid >> 1, wid & 1);
}

__global__ __launch_bounds__(128, 2)
void gemm_out(const bf16* __restrict__ A, const bf16* __restrict__ W,
              float* __restrict__ C, int N, int K,
              const float* __restrict__ bias, const float* __restrict__ res) {
    extern __shared__ bf16 sm[];
    const int t = threadIdx.x;
    const int lane = t & 31, wid = t >> 5;
    gemm_core(A, W, C, N, K, blockIdx.y * 128, blockIdx.x * 128, false,
              bias, res, sm, smem_u32(sm), t, lane, wid >> 1, wid & 1);
}

// ---------------- fp32 -> bf16 conversion ------------------------------------
__global__ void f2bf(const float* __restrict__ x, bf16* __restrict__ y, int n4) {
    int i = blockIdx.x * blockDim.x + threadIdx.x;
    if (i >= n4) return;
    float4 v = ((const float4*)x)[i];
    uint2 o;
    o.x = pack_bf2(v.x, v.y);
    o.y = pack_bf2(v.z, v.w);
    ((uint2*)y)[i] = o;
}

struct ConvBatch { const float* src[6]; bf16* dst[6]; int n4[6]; };
__global__ void f2bf_batch(ConvBatch cb) {
    int seg = blockIdx.y;
    int i = blockIdx.x * blockDim.x + threadIdx.x;
    if (i >= cb.n4[seg]) return;
    float4 v = ((const float4*)cb.src[seg])[i];
    uint2 o;
    o.x = pack_bf2(v.x, v.y);
    o.y = pack_bf2(v.z, v.w);
    ((uint2*)cb.dst[seg])[i] = o;
}

// ---------------- gather encoder tokens (bf16) ------------------------------
__global__ void gather_tokens(const float* __restrict__ enc) {
    int i = blockIdx.x * blockDim.x + threadIdx.x;
    if (i >= Bsz*NTOK*CRS) return;
    int c = i % CRS;
    int tt = (i / CRS) % NTOK;
    int b = i / (CRS*NTOK);
    g_dis [i] = __float2bfloat16_rn(enc[((long)b*ETOK + tt)        * CRS + c]);
    g_anat[i] = __float2bfloat16_rn(enc[((long)b*ETOK + NTOK + tt) * CRS + c]);
}

// ---------------- per-batch gate scalars -----------------------------------
__global__ void gate_kernel(const float* __restrict__ w_gate,
                            const float* __restrict__ b_gate,
                            const float* __restrict__ anat_logit,
                            const float* __restrict__ dis_logit) {
    int b = blockIdx.x;
    __shared__ float red[256];
    float partial = 0.f;
    for (int c = threadIdx.x; c < CRS; c += 256) {
        float s = 0.f;
        #pragma unroll
        for (int t = 0; t < NTOK; t++)
            s += __bfloat162float(g_dis[(b*NTOK + t)*CRS + c]);
        partial += (s * (1.0f/NTOK)) * w_gate[c];
    }
    red[threadIdx.x] = partial;
    __syncthreads();
    for (int off = 128; off > 0; off >>= 1) {
        if (threadIdx.x < off) red[threadIdx.x] += red[threadIdx.x + off];
        __syncthreads();
    }
    if (threadIdx.x == 0) {
        float shift = red[0] + b_gate[0];
        g_gate[b*2+0] = 1.0f / (1.0f + expf(-(anat_logit[0] - shift)));
        g_gate[b*2+1] = 1.0f / (1.0f + expf(-(dis_logit[0]  + shift)));
    }
}

// ---------------- mma attention: one CTA = 128 queries x 1 head -------------
#define VP 24

__device__ __forceinline__ void attend_branch(
    const bf16* sK, const bf16* sV, float gate, int lane,
    const uint32_t (&qf)[2][4][4], float (&out)[2][8][4])
{
    uint32_t bk[2][4][2];
    #pragma unroll
    for (int n = 0; n < 2; n++)
        #pragma unroll
        for (int k = 0; k < 4; k++) {
            const bf16* p = &sK[(n*8 + (lane >> 2))*72 + k*16 + 2*(lane & 3)];
            bk[n][k][0] = *(const uint32_t*)p;
            bk[n][k][1] = *(const uint32_t*)(p + 8);
        }
    uint32_t bv[8][2];
    #pragma unroll
    for (int n8 = 0; n8 < 8; n8++) {
        const bf16* p = &sV[(n8*8 + (lane >> 2))*VP + 2*(lane & 3)];
        bv[n8][0] = *(const uint32_t*)p;
        bv[n8][1] = *(const uint32_t*)(p + 8);
    }

    float sc[2][2][4];
    #pragma unroll
    for (int m = 0; m < 2; m++)
        #pragma unroll
        for (int n = 0; n < 2; n++) {
            #pragma unroll
            for (int r = 0; r < 4; r++) sc[m][n][r] = 0.f;
            #pragma unroll
            for (int k = 0; k < 4; k++)
                mma16(sc[m][n], qf[m][k], bk[n][k]);
        }

    #pragma unroll
    for (int m = 0; m < 2; m++) {
        float v[2][4];
        #pragma unroll
        for (int n = 0; n < 2; n++)
            #pragma unroll
            for (int r = 0; r < 4; r++) v[n][r] = sc[m][n][r] * SCALE;

        float mx0 = fmaxf(fmaxf(v[0][0], v[0][1]), fmaxf(v[1][0], v[1][1]));
        float mx1 = fmaxf(fmaxf(v[0][2], v[0][3]), fmaxf(v[1][2], v[1][3]));
        mx0 = fmaxf(mx0, __shfl_xor_sync(0xffffffffu, mx0, 1));
        mx0 = fmaxf(mx0, __shfl_xor_sync(0xffffffffu, mx0, 2));
        mx1 = fmaxf(mx1, __shfl_xor_sync(0xffffffffu, mx1, 1));
        mx1 = fmaxf(mx1, __shfl_xor_sync(0xffffffffu, mx1, 2));

        float e[2][4];
        #pragma unroll
        for (int n = 0; n < 2; n++) {
            e[n][0] = expf(v[n][0] - mx0);
            e[n][1] = expf(v[n][1] - mx0);
            e[n][2] = expf(v[n][2] - mx1);
            e[n][3] = expf(v[n][3] - mx1);
        }
        float s0 = e[0][0] + e[0][1] + e[1][0] + e[1][1];
        float s1 = e[0][2] + e[0][3] + e[1][2] + e[1][3];
        s0 += __shfl_xor_sync(0xffffffffu, s0, 1);
        s0 += __shfl_xor_sync(0xffffffffu, s0, 2);
        s1 += __shfl_xor_sync(0xffffffffu, s1, 1);
        s1 += __shfl_xor_sync(0xffffffffu, s1, 2);
        float i0 = gate / s0, i1 = gate / s1;

        uint32_t pf[4];
        pf[0] = pack_bf2(e[0][0]*i0, e[0][1]*i0);
        pf[1] = pack_bf2(e[0][2]*i1, e[0][3]*i1);
        pf[2] = pack_bf2(e[1][0]*i0, e[1][1]*i0);
        pf[3] = pack_bf2(e[1][2]*i1, e[1][3]*i1);

        #pragma unroll
        for (int n8 = 0; n8 < 8; n8++)
            mma16(out[m][n8], pf, bv[n8]);
    }
}

__global__ __launch_bounds__(128)
void attn_mma() {
    __shared__ bf16 sQ[128*72];
    __shared__ bf16 sKa[16*72], sKd[16*72];
    __shared__ bf16 sVa[64*VP], sVd[64*VP];
    const int b = blockIdx.z, h = blockIdx.y, bx = blockIdx.x;
    const int t = threadIdx.x, lane = t & 31, w = t >> 5;

    const long qbase = ((long)(b*Ssz) + bx*128) * Dsz + h*HD;
    #pragma unroll
    for (int i = 0; i < 8; i++) {
        int idx = i*128 + t;
        int row = idx >> 3, c8 = idx & 7;
        uint4 v = *(const uint4*)(g_qb + qbase + (long)row*Dsz + c8*8);
        *(uint4*)&sQ[row*72 + c8*8] = v;
    }
    {
        const float* ka = g_ka + ((long)b*NTOK)*Dsz + h*HD;
        const float* kd = g_kd + ((long)b*NTOK)*Dsz + h*HD;
        #pragma unroll
        for (int i = 0; i < 4; i++) {
            int idx = i*128 + t;
            int d2 = idx & 31, tok = idx >> 5;
            float2 va = *(const float2*)(ka + (long)tok*Dsz + 2*d2);
            float2 vd = *(const float2*)(kd + (long)tok*Dsz + 2*d2);
            *(uint32_t*)&sKa[tok*72 + 2*d2] = pack_bf2(va.x, va.y);
            *(uint32_t*)&sKd[tok*72 + 2*d2] = pack_bf2(vd.x, vd.y);
        }
    }
    {
        const float* va = g_va + ((long)b*NTOK)*Dsz + h*HD;
        const float* vd = g_vd + ((long)b*NTOK)*Dsz + h*HD;
        #pragma unroll
        for (int i = 0; i < 8; i++) {
            int idx = i*128 + t;
            int d = idx & 63, tok = idx >> 6;
            sVa[d*VP + tok] = __float2bfloat16_rn(va[(long)tok*Dsz + d]);
            sVd[d*VP + tok] = __float2bfloat16_rn(vd[(long)tok*Dsz + d]);
        }
    }
    __syncthreads();

    const float ga = g_gate[b*2+0], gd = g_gate[b*2+1];

    uint32_t qf[2][4][4];
    #pragma unroll
    for (int m = 0; m < 2; m++)
        #pragma unroll
        for (int k = 0; k < 4; k++) {
            uint32_t addr = smem_u32(
                &sQ[(w*32 + m*16 + (lane & 15))*72 + k*16 + ((lane >> 4) << 3)]);
            ldsm4(qf[m][k], addr);
        }

    float out[2][8][4];
    #pragma unroll
    for (int m = 0; m < 2; m++)
        #pragma unroll
        for (int n = 0; n < 8; n++)
            #pragma unroll
            for (int r = 0; r < 4; r++) out[m][n][r] = 0.f;

    attend_branch(sKa, sVa, ga, lane, qf, out);
    attend_branch(sKd, sVd, gd, lane, qf, out);

    const long zbase = ((long)(b*Ssz) + bx*128 + w*32) * Dsz + h*HD;
    const int r = lane >> 2, c = 2 * (lane & 3);
    #pragma unroll
    for (int m = 0; m < 2; m++)
        #pragma unroll
        for (int n8 = 0; n8 < 8; n8++) {
            long ro = zbase + (long)(m*16 + r) * Dsz + n8*8 + c;
            *(uint32_t*)(g_z + ro)          = pack_bf2(out[m][n8][0], out[m][n8][1]);
            *(uint32_t*)(g_z + ro + 8*Dsz)  = pack_bf2(out[m][n8][2], out[m][n8][3]);
        }
}

// ---------------- launch ----------------------------------------------------
extern "C" void kernel_launch(void* const* d_in, const int* in_sizes, int n_in,
                              void* d_out, int out_size) {
    const float* hidden  = (const float*)d_in[0];
    const float* enc     = (const float*)d_in[1];
    const float* w_q     = (const float*)d_in[2];
    const float* w_k     = (const float*)d_in[3];
    const float* w_v     = (const float*)d_in[4];
    const float* w_k_dis = (const float*)d_in[5];
    const float* w_v_dis = (const float*)d_in[6];
    const float* w_gate  = (const float*)d_in[7];
    const float* b_gate  = (const float*)d_in[8];
    const float* a_logit = (const float*)d_in[9];
    const float* d_logit = (const float*)d_in[10];
    const float* w_out   = (const float*)d_in[11];
    const float* b_out   = (const float*)d_in[12];
    float* out = (float*)d_out;

    bf16 *anat_p, *dis_p, *z_p, *hidb_p, *qb_p, *wq_p, *wout_p, *wka_p, *wva_p, *wkd_p, *wvd_p;
    float *ka_p, *va_p, *kd_p, *vd_p;
    cudaGetSymbolAddress((void**)&anat_p, g_anat);
    cudaGetSymbolAddress((void**)&dis_p,  g_dis);
    cudaGetSymbolAddress((void**)&ka_p,   g_ka);
    cudaGetSymbolAddress((void**)&va_p,   g_va);
    cudaGetSymbolAddress((void**)&kd_p,   g_kd);
    cudaGetSymbolAddress((void**)&vd_p,   g_vd);
    cudaGetSymbolAddress((void**)&qb_p,   g_qb);
    cudaGetSymbolAddress((void**)&z_p,    g_z);
    cudaGetSymbolAddress((void**)&hidb_p, g_hidb);
    cudaGetSymbolAddress((void**)&wq_p,   g_wq);
    cudaGetSymbolAddress((void**)&wout_p, g_wout);
    cudaGetSymbolAddress((void**)&wka_p,  g_wka);
    cudaGetSymbolAddress((void**)&wva_p,  g_wva);
    cudaGetSymbolAddress((void**)&wkd_p,  g_wkd);
    cudaGetSymbolAddress((void**)&wvd_p,  g_wvd);

    cudaFuncSetAttribute(proj_all, cudaFuncAttributeMaxDynamicSharedMemorySize, GEMM_SMEM);
    cudaFuncSetAttribute(gemm_out, cudaFuncAttributeMaxDynamicSharedMemorySize, GEMM_SMEM);

    // conversions: hidden (big) + 6 weights (batched single launch)
    {
        int n4 = MS*Dsz/4;
        f2bf<<<(n4 + 255)/256, 256>>>(hidden, hidb_p, n4);
        ConvBatch cb;
        int w4 = Dsz*Dsz/4, k4 = Dsz*CRS/4;
        cb.src[0] = w_q;     cb.dst[0] = wq_p;   cb.n4[0] = w4;
        cb.src[1] = w_out;   cb.dst[1] = wout_p; cb.n4[1] = w4;
        cb.src[2] = w_k;     cb.dst[2] = wka_p;  cb.n4[2] = k4;
        cb.src[3] = w_v;     cb.dst[3] = wva_p;  cb.n4[3] = k4;
        cb.src[4] = w_k_dis; cb.dst[4] = wkd_p;  cb.n4[4] = k4;
        cb.src[5] = w_v_dis; cb.dst[5] = wvd_p;  cb.n4[5] = k4;
        dim3 grid((w4 + 255)/256, 6);
        f2bf_batch<<<grid, 256>>>(cb);
    }
    { int n = Bsz*NTOK*CRS; gather_tokens<<<(n + 255)/256, 256>>>(enc); }
    gate_kernel<<<Bsz, 256>>>(w_gate, b_gate, a_logit, d_logit);

    // merged Q + KV projections (one launch, 2720 CTAs of 128 threads)
    {
        ProjBatch pb;
        pb.A[0] = hidb_p; pb.W[0] = wq_p;  pb.C[0] = qb_p; pb.K[0] = Dsz;
        pb.A[1] = anat_p; pb.W[1] = wka_p; pb.C[1] = ka_p; pb.K[1] = CRS;
        pb.A[2] = anat_p; pb.W[2] = wva_p; pb.C[2] = va_p; pb.K[2] = CRS;
        pb.A[3] = dis_p;  pb.W[3] = wkd_p; pb.C[3] = kd_p; pb.K[3] = CRS;
        pb.A[4] = dis_p;  pb.W[4] = wvd_p; pb.C[4] = vd_p; pb.K[4] = CRS;
        dim3 grid(Dsz/128, 256 + 16);
        proj_all<<<grid, 128, GEMM_SMEM>>>(pb);
    }
    // mma attention + gating
    {
        dim3 grid(Ssz/128, HEADS, Bsz);
        attn_mma<<<grid, 128>>>();
    }
    // out projection + bias + residual
    {
        dim3 grid(Dsz/128, MS/128);
        gemm_out<<<grid, 128, GEMM_SMEM>>>(z_p, wout_p, out, Dsz, Dsz, b_out, hidden);
    }
}